// round 1
// baseline (speedup 1.0000x reference)
#include <cuda_runtime.h>

// Problem constants
#define TOK     2048      // B*S
#define DMODEL  1024
#define DINNER  2048
#define DSTATE  16
#define SEQLEN  1024
#define NBATCH  2

// Scratch (device globals — no runtime allocation allowed)
__device__ float g_xproj[TOK * DINNER];   // x_proj   [T, d_inner]
__device__ float g_delta[TOK * DINNER];   // relu(delta_proj)
__device__ float g_gate [TOK * DINNER];   // sigmoid gate
__device__ float g_gss  [TOK * DINNER];   // gate * (scan_out + x*D)

// ---------------------------------------------------------------------------
// Tiled fp32 GEMM:  C[m,n] = sum_k A[m,k] * W[n,k] + bias[n]
// Both A and W are K-major (row-major with K contiguous).
// BM=BN=128, BK=16, 256 threads, 8x8 per-thread tile.
// EPI 0: N=4096; cols<2048 -> g_xproj, cols>=2048 -> relu -> g_delta
// EPI 1: sigmoid -> g_gate
// EPI 2: A is g_gss (ignore arg), plain store to C0 (= d_out)
// ---------------------------------------------------------------------------
template <int EPI>
__global__ void __launch_bounds__(256)
gemm_tn(const float* __restrict__ A, const float* __restrict__ W,
        const float* __restrict__ bias, float* __restrict__ C0,
        int M, int N, int K)
{
    const int BM = 128, BN = 128, BK = 16;
    __shared__ float As[BK][BM + 4];
    __shared__ float Ws[BK][BN + 4];

    const float* Ap = (EPI == 2) ? (const float*)g_gss : A;

    int tid  = threadIdx.x;
    int trow = tid >> 4;        // 0..15
    int tcol = tid & 15;        // 0..15
    int rowBase = blockIdx.y * BM;
    int colBase = blockIdx.x * BN;

    int loadRow = tid >> 2;         // 0..63
    int loadCol = (tid & 3) * 4;    // 0,4,8,12

    const float* Ag = Ap + (size_t)(rowBase + loadRow) * K + loadCol;
    const float* Wg = W  + (size_t)(colBase + loadRow) * K + loadCol;

    float acc[8][8];
#pragma unroll
    for (int i = 0; i < 8; i++)
#pragma unroll
        for (int j = 0; j < 8; j++) acc[i][j] = 0.0f;

    for (int kt = 0; kt < K; kt += BK) {
        float4 a0 = *(const float4*)(Ag + kt);
        float4 a1 = *(const float4*)(Ag + (size_t)64 * K + kt);
        float4 w0 = *(const float4*)(Wg + kt);
        float4 w1 = *(const float4*)(Wg + (size_t)64 * K + kt);

        As[loadCol + 0][loadRow]      = a0.x;
        As[loadCol + 1][loadRow]      = a0.y;
        As[loadCol + 2][loadRow]      = a0.z;
        As[loadCol + 3][loadRow]      = a0.w;
        As[loadCol + 0][loadRow + 64] = a1.x;
        As[loadCol + 1][loadRow + 64] = a1.y;
        As[loadCol + 2][loadRow + 64] = a1.z;
        As[loadCol + 3][loadRow + 64] = a1.w;

        Ws[loadCol + 0][loadRow]      = w0.x;
        Ws[loadCol + 1][loadRow]      = w0.y;
        Ws[loadCol + 2][loadRow]      = w0.z;
        Ws[loadCol + 3][loadRow]      = w0.w;
        Ws[loadCol + 0][loadRow + 64] = w1.x;
        Ws[loadCol + 1][loadRow + 64] = w1.y;
        Ws[loadCol + 2][loadRow + 64] = w1.z;
        Ws[loadCol + 3][loadRow + 64] = w1.w;

        __syncthreads();

#pragma unroll
        for (int kk = 0; kk < BK; kk++) {
            float ra[8], rb[8];
            *(float4*)&ra[0] = *(const float4*)&As[kk][trow * 8];
            *(float4*)&ra[4] = *(const float4*)&As[kk][trow * 8 + 4];
            *(float4*)&rb[0] = *(const float4*)&Ws[kk][tcol * 8];
            *(float4*)&rb[4] = *(const float4*)&Ws[kk][tcol * 8 + 4];
#pragma unroll
            for (int i = 0; i < 8; i++)
#pragma unroll
                for (int j = 0; j < 8; j++)
                    acc[i][j] += ra[i] * rb[j];
        }
        __syncthreads();
    }

    // Epilogue: vectorized float4 stores
#pragma unroll
    for (int i = 0; i < 8; i++) {
        int row = rowBase + trow * 8 + i;
#pragma unroll
        for (int j4 = 0; j4 < 2; j4++) {
            int col = colBase + tcol * 8 + j4 * 4;
            float4 v;
            v.x = acc[i][j4 * 4 + 0] + bias[col + 0];
            v.y = acc[i][j4 * 4 + 1] + bias[col + 1];
            v.z = acc[i][j4 * 4 + 2] + bias[col + 2];
            v.w = acc[i][j4 * 4 + 3] + bias[col + 3];
            if (EPI == 0) {
                if (col < DINNER) {
                    *(float4*)&g_xproj[(size_t)row * DINNER + col] = v;
                } else {
                    v.x = fmaxf(v.x, 0.0f); v.y = fmaxf(v.y, 0.0f);
                    v.z = fmaxf(v.z, 0.0f); v.w = fmaxf(v.w, 0.0f);
                    *(float4*)&g_delta[(size_t)row * DINNER + (col - DINNER)] = v;
                }
            } else if (EPI == 1) {
                v.x = 1.0f / (1.0f + __expf(-v.x));
                v.y = 1.0f / (1.0f + __expf(-v.y));
                v.z = 1.0f / (1.0f + __expf(-v.z));
                v.w = 1.0f / (1.0f + __expf(-v.w));
                *(float4*)&g_gate[(size_t)row * DINNER + col] = v;
            } else {
                *(float4*)&C0[(size_t)row * N + col] = v;
            }
        }
    }
}

// ---------------------------------------------------------------------------
// Selective scan.
// One thread per (batch, channel, state). 16 lanes = 16 states of one channel.
// h_t = h_{t-1} * exp(A*dt) + (x*dt)*B ;  y_t = sum_s h_s * c0_s
// g_gss = gate * (y + x*D)
// ---------------------------------------------------------------------------
__global__ void __launch_bounds__(256)
scan_kernel(const float* __restrict__ A_log, const float* __restrict__ B_mat,
            const float* __restrict__ C_mat, const float* __restrict__ D_vec)
{
    int slot = blockIdx.x * (blockDim.x >> 4) + (threadIdx.x >> 4); // 0..4095
    int s    = threadIdx.x & 15;
    int b    = slot >> 11;       // 0..1
    int ch   = slot & (DINNER - 1);

    float As  = -__expf(A_log[ch * DSTATE + s]);
    float Bs  = B_mat[ch * DSTATE + s];
    float cs  = C_mat[s];                 // row 0 of C only
    float Dch = D_vec[ch];

    float h = 0.0f;
    size_t base = (size_t)b * SEQLEN * DINNER + ch;

#pragma unroll 4
    for (int t = 0; t < SEQLEN; t++) {
        size_t idx = base + (size_t)t * DINNER;
        float dt = g_delta[idx];
        float xt = g_xproj[idx];
        float a  = __expf(As * dt);
        h = h * a + (xt * dt) * Bs;
        float p = h * cs;
        p += __shfl_xor_sync(0xffffffffu, p, 1);
        p += __shfl_xor_sync(0xffffffffu, p, 2);
        p += __shfl_xor_sync(0xffffffffu, p, 4);
        p += __shfl_xor_sync(0xffffffffu, p, 8);
        if (s == 0) {
            g_gss[idx] = g_gate[idx] * (p + xt * Dch);
        }
    }
}

// ---------------------------------------------------------------------------
extern "C" void kernel_launch(void* const* d_in, const int* in_sizes, int n_in,
                              void* d_out, int out_size)
{
    const float* x      = (const float*)d_in[0];
    const float* W_in   = (const float*)d_in[1];
    const float* b_in   = (const float*)d_in[2];
    const float* W_gate = (const float*)d_in[3];
    const float* b_gate = (const float*)d_in[4];
    const float* W_out  = (const float*)d_in[5];
    const float* b_out  = (const float*)d_in[6];
    const float* A_log  = (const float*)d_in[7];
    const float* B_mat  = (const float*)d_in[8];
    const float* C_mat  = (const float*)d_in[9];
    const float* D_vec  = (const float*)d_in[10];
    float* out = (float*)d_out;

    dim3 blk(256);

    // proj = x @ W_in^T + b_in  -> x_proj | relu(delta)
    gemm_tn<0><<<dim3(4096 / 128, TOK / 128), blk>>>(x, W_in, b_in, nullptr,
                                                     TOK, 2 * DINNER, DMODEL);
    // gate = sigmoid(x @ W_gate^T + b_gate)
    gemm_tn<1><<<dim3(2048 / 128, TOK / 128), blk>>>(x, W_gate, b_gate, nullptr,
                                                     TOK, DINNER, DMODEL);
    // selective scan + gate multiply
    scan_kernel<<<(NBATCH * DINNER * DSTATE) / 256, 256>>>(A_log, B_mat, C_mat, D_vec);

    // out = g_gss @ W_out^T + b_out
    gemm_tn<2><<<dim3(1024 / 128, TOK / 128), blk>>>(nullptr, W_out, b_out, out,
                                                     TOK, DMODEL, DINNER);
}

// round 3
// speedup vs baseline: 1.4146x; 1.4146x over previous
#include <cuda_runtime.h>
#include <cuda_bf16.h>
#include <cstdint>

// Problem constants
#define TOK     2048      // B*S
#define DMODEL  1024
#define DINNER  2048
#define DSTATE  16
#define SEQLEN  1024
#define NBATCH  2

// ---------------------------------------------------------------------------
// Device-global scratch (no runtime allocation allowed)
// ---------------------------------------------------------------------------
__device__ float g_xproj[TOK * DINNER];
__device__ float g_delta[TOK * DINNER];
__device__ float g_gate [TOK * DINNER];

__device__ __nv_bfloat16 g_x_hi [TOK * DMODEL],         g_x_lo [TOK * DMODEL];
__device__ __nv_bfloat16 g_win_hi[2 * DINNER * DMODEL], g_win_lo[2 * DINNER * DMODEL];
__device__ __nv_bfloat16 g_wg_hi [DINNER * DMODEL],     g_wg_lo [DINNER * DMODEL];
__device__ __nv_bfloat16 g_wo_hi [DMODEL * DINNER],     g_wo_lo [DMODEL * DINNER];
__device__ __nv_bfloat16 g_gss_hi[TOK * DINNER],        g_gss_lo[TOK * DINNER];

// ---------------------------------------------------------------------------
// PTX helpers (base-target-safe: cp.async / ldmatrix / mma.sync)
// ---------------------------------------------------------------------------
__device__ __forceinline__ uint32_t smem_u32(const void* p) {
    uint32_t a;
    asm("{ .reg .u64 t; cvta.to.shared.u64 t, %1; cvt.u32.u64 %0, t; }" : "=r"(a) : "l"(p));
    return a;
}
__device__ __forceinline__ void cpa16(uint32_t s, const void* g) {
    asm volatile("cp.async.cg.shared.global [%0], [%1], 16;" :: "r"(s), "l"(g) : "memory");
}
__device__ __forceinline__ void cpa_commit() {
    asm volatile("cp.async.commit_group;" ::: "memory");
}
template <int N>
__device__ __forceinline__ void cpa_wait() {
    asm volatile("cp.async.wait_group %0;" :: "n"(N) : "memory");
}
__device__ __forceinline__ void ldsm4(uint32_t& r0, uint32_t& r1, uint32_t& r2,
                                      uint32_t& r3, uint32_t a) {
    asm volatile("ldmatrix.sync.aligned.m8n8.x4.shared.b16 {%0,%1,%2,%3}, [%4];"
                 : "=r"(r0), "=r"(r1), "=r"(r2), "=r"(r3) : "r"(a));
}
__device__ __forceinline__ void mma16816(float* d, const uint32_t* a, const uint32_t* b) {
    asm volatile(
        "mma.sync.aligned.m16n8k16.row.col.f32.bf16.bf16.f32 "
        "{%0,%1,%2,%3}, {%4,%5,%6,%7}, {%8,%9}, {%0,%1,%2,%3};"
        : "+f"(d[0]), "+f"(d[1]), "+f"(d[2]), "+f"(d[3])
        : "r"(a[0]), "r"(a[1]), "r"(a[2]), "r"(a[3]), "r"(b[0]), "r"(b[1]));
}

// ---------------------------------------------------------------------------
// SMEM layout (dynamic):
//   stage s (s=0,1) at s*40960:
//     A_hi @ +0, A_lo @ +10240, B_hi @ +20480, B_lo @ +30720
//   each tile: 128 rows x 80 bytes (32 bf16 data + 16B pad)  = 10240 B
//   bias (128 f32) @ 81920
// ---------------------------------------------------------------------------
#define ROWB        80
#define TILE_B      (128 * ROWB)
#define STAGE_B     (4 * TILE_B)
#define SM_BIAS_OFF (2 * STAGE_B)
#define SMEM_TOTAL  (SM_BIAS_OFF + 512)

// issue cp.async for one 128x32 bf16 tile (K-major, ld = K) into padded smem
__device__ __forceinline__ void tile_cpasync(const __nv_bfloat16* __restrict__ g,
                                             int rowBase, int kt, int ld,
                                             uint32_t sdst, int tid) {
#pragma unroll
    for (int i = 0; i < 2; i++) {
        int seg = tid + i * 256;        // 0..511
        int r   = seg >> 2;             // 0..127
        int c   = seg & 3;              // 16B chunk (8 bf16)
        cpa16(sdst + r * ROWB + c * 16,
              g + (size_t)(rowBase + r) * ld + kt + c * 8);
    }
}

// ---------------------------------------------------------------------------
// Split-bf16 tensor-core GEMM:  C[m,n] = sum_k A[m,k]*W[n,k] + bias[n]
// A ~ Ah+Al, W ~ Wh+Wl ;  acc += Ah*Wh + Ah*Wl + Al*Wh  (fp32)
// EPI 0: N=4096 -> g_xproj (col<2048) | relu -> g_delta
// EPI 1: sigmoid -> g_gate
// EPI 2: plain +bias -> Cout
// ---------------------------------------------------------------------------
template <int EPI>
__global__ void __launch_bounds__(256, 1)
gemm_mma(const __nv_bfloat16* __restrict__ Ah, const __nv_bfloat16* __restrict__ Al,
         const __nv_bfloat16* __restrict__ Wh, const __nv_bfloat16* __restrict__ Wl,
         const float* __restrict__ bias, float* __restrict__ Cout, int N, int K)
{
    extern __shared__ char smem[];
    uint32_t sbase = smem_u32(smem);

    const int tid = threadIdx.x;
    const int wid = tid >> 5;
    const int l   = tid & 31;
    const int wm  = wid >> 2;           // 0..1
    const int wn  = wid & 3;            // 0..3
    const int mo  = wm * 64;            // warp M offset in tile
    const int no  = wn * 32;            // warp N offset in tile

    const int rowBase = blockIdx.y * 128;
    const int colBase = blockIdx.x * 128;

    if (tid < 128)
        *reinterpret_cast<float*>(smem + SM_BIAS_OFF + tid * 4) = bias[colBase + tid];

    // ldmatrix lane address components (byte offsets within a tile)
    const uint32_t aRow = (uint32_t)((mo + (l & 15)) * ROWB + ((l >> 4) * 16));
    const uint32_t bRow = (uint32_t)((no + (l & 7) + ((l & 16) ? 8 : 0)) * ROWB
                                     + (((l >> 3) & 1) * 16));

    float acc[4][4][4];
#pragma unroll
    for (int mi = 0; mi < 4; mi++)
#pragma unroll
        for (int ni = 0; ni < 4; ni++)
#pragma unroll
            for (int r = 0; r < 4; r++) acc[mi][ni][r] = 0.0f;

    const int NC = K / 32;

    // prologue: chunk 0 -> stage 0
    {
        uint32_t st = sbase;
        tile_cpasync(Ah, rowBase, 0, K, st,              tid);
        tile_cpasync(Al, rowBase, 0, K, st + TILE_B,     tid);
        tile_cpasync(Wh, colBase, 0, K, st + 2 * TILE_B, tid);
        tile_cpasync(Wl, colBase, 0, K, st + 3 * TILE_B, tid);
        cpa_commit();
    }

    for (int c = 0; c < NC; c++) {
        if (c + 1 < NC) {
            uint32_t st = sbase + ((c + 1) & 1) * STAGE_B;
            int kt = (c + 1) * 32;
            tile_cpasync(Ah, rowBase, kt, K, st,              tid);
            tile_cpasync(Al, rowBase, kt, K, st + TILE_B,     tid);
            tile_cpasync(Wh, colBase, kt, K, st + 2 * TILE_B, tid);
            tile_cpasync(Wl, colBase, kt, K, st + 3 * TILE_B, tid);
            cpa_commit();
            cpa_wait<1>();
        } else {
            cpa_wait<0>();
        }
        __syncthreads();

        uint32_t st = sbase + (c & 1) * STAGE_B;
#pragma unroll
        for (int ks = 0; ks < 2; ks++) {
            uint32_t ah[4][4], al[4][4], bh[8], bl[8];
#pragma unroll
            for (int mi = 0; mi < 4; mi++) {
                uint32_t ad = st + aRow + mi * (16 * ROWB) + ks * 32;
                ldsm4(ah[mi][0], ah[mi][1], ah[mi][2], ah[mi][3], ad);
                ldsm4(al[mi][0], al[mi][1], al[mi][2], al[mi][3], ad + TILE_B);
            }
#pragma unroll
            for (int np = 0; np < 2; np++) {
                uint32_t bd = st + 2 * TILE_B + bRow + np * (16 * ROWB) + ks * 32;
                ldsm4(bh[np * 4 + 0], bh[np * 4 + 1], bh[np * 4 + 2], bh[np * 4 + 3], bd);
                ldsm4(bl[np * 4 + 0], bl[np * 4 + 1], bl[np * 4 + 2], bl[np * 4 + 3],
                      bd + TILE_B);
            }
#pragma unroll
            for (int mi = 0; mi < 4; mi++)
#pragma unroll
                for (int ni = 0; ni < 4; ni++) {
                    mma16816(acc[mi][ni], ah[mi], &bh[ni * 2]);
                    mma16816(acc[mi][ni], ah[mi], &bl[ni * 2]);
                    mma16816(acc[mi][ni], al[mi], &bh[ni * 2]);
                }
        }
        __syncthreads();
    }

    // Epilogue
    const float* sb = reinterpret_cast<const float*>(smem + SM_BIAS_OFF);
    const int g  = l >> 2;
    const int t4 = l & 3;
#pragma unroll
    for (int mi = 0; mi < 4; mi++) {
#pragma unroll
        for (int ni = 0; ni < 4; ni++) {
            int bc   = no + ni * 8 + 2 * t4;     // col within block
            int col  = colBase + bc;
            int row0 = rowBase + mo + mi * 16 + g;
            int row1 = row0 + 8;
            float2 v0, v1;
            v0.x = acc[mi][ni][0] + sb[bc];
            v0.y = acc[mi][ni][1] + sb[bc + 1];
            v1.x = acc[mi][ni][2] + sb[bc];
            v1.y = acc[mi][ni][3] + sb[bc + 1];
            if (EPI == 0) {
                if (colBase < DINNER) {
                    *reinterpret_cast<float2*>(&g_xproj[(size_t)row0 * DINNER + col]) = v0;
                    *reinterpret_cast<float2*>(&g_xproj[(size_t)row1 * DINNER + col]) = v1;
                } else {
                    v0.x = fmaxf(v0.x, 0.f); v0.y = fmaxf(v0.y, 0.f);
                    v1.x = fmaxf(v1.x, 0.f); v1.y = fmaxf(v1.y, 0.f);
                    int cc = col - DINNER;
                    *reinterpret_cast<float2*>(&g_delta[(size_t)row0 * DINNER + cc]) = v0;
                    *reinterpret_cast<float2*>(&g_delta[(size_t)row1 * DINNER + cc]) = v1;
                }
            } else if (EPI == 1) {
                v0.x = 1.f / (1.f + __expf(-v0.x));
                v0.y = 1.f / (1.f + __expf(-v0.y));
                v1.x = 1.f / (1.f + __expf(-v1.x));
                v1.y = 1.f / (1.f + __expf(-v1.y));
                *reinterpret_cast<float2*>(&g_gate[(size_t)row0 * DINNER + col]) = v0;
                *reinterpret_cast<float2*>(&g_gate[(size_t)row1 * DINNER + col]) = v1;
            } else {
                *reinterpret_cast<float2*>(&Cout[(size_t)row0 * N + col]) = v0;
                *reinterpret_cast<float2*>(&Cout[(size_t)row1 * N + col]) = v1;
            }
        }
    }
}

// ---------------------------------------------------------------------------
// fp32 -> bf16 hi/lo split
// ---------------------------------------------------------------------------
__global__ void __launch_bounds__(256)
split_kernel(const float* __restrict__ src, __nv_bfloat16* __restrict__ hi,
             __nv_bfloat16* __restrict__ lo, int n)
{
    int i = blockIdx.x * blockDim.x + threadIdx.x;
    if (i < n) {
        float v = src[i];
        __nv_bfloat16 h = __float2bfloat16(v);
        float r = v - __bfloat162float(h);
        hi[i] = h;
        lo[i] = __float2bfloat16(r);
    }
}

// ---------------------------------------------------------------------------
// Selective scan. One thread per (batch, channel, state).
// h_t = h*exp(A*dt) + (x*dt)*B ;  y = sum_s h_s*c0_s ; out = gate*(y + x*D)
// Output written as split bf16 (feeds gemm<2> directly).
// ---------------------------------------------------------------------------
__global__ void __launch_bounds__(256)
scan_kernel(const float* __restrict__ A_log, const float* __restrict__ B_mat,
            const float* __restrict__ C_mat, const float* __restrict__ D_vec)
{
    int slot = blockIdx.x * (blockDim.x >> 4) + (threadIdx.x >> 4);
    int s    = threadIdx.x & 15;
    int b    = slot >> 11;
    int ch   = slot & (DINNER - 1);

    float As  = -__expf(A_log[ch * DSTATE + s]);
    float Bs  = B_mat[ch * DSTATE + s];
    float cs  = C_mat[s];
    float Dch = D_vec[ch];

    float h = 0.0f;
    size_t base = (size_t)b * SEQLEN * DINNER + ch;

#pragma unroll 4
    for (int t = 0; t < SEQLEN; t++) {
        size_t idx = base + (size_t)t * DINNER;
        float dt = g_delta[idx];
        float xt = g_xproj[idx];
        float a  = __expf(As * dt);
        h = h * a + (xt * dt) * Bs;
        float p = h * cs;
        p += __shfl_xor_sync(0xffffffffu, p, 1);
        p += __shfl_xor_sync(0xffffffffu, p, 2);
        p += __shfl_xor_sync(0xffffffffu, p, 4);
        p += __shfl_xor_sync(0xffffffffu, p, 8);
        if (s == 0) {
            float v = g_gate[idx] * (p + xt * Dch);
            __nv_bfloat16 vh = __float2bfloat16(v);
            g_gss_hi[idx] = vh;
            g_gss_lo[idx] = __float2bfloat16(v - __bfloat162float(vh));
        }
    }
}

// ---------------------------------------------------------------------------
extern "C" void kernel_launch(void* const* d_in, const int* in_sizes, int n_in,
                              void* d_out, int out_size)
{
    const float* x      = (const float*)d_in[0];
    const float* W_in   = (const float*)d_in[1];
    const float* b_in   = (const float*)d_in[2];
    const float* W_gate = (const float*)d_in[3];
    const float* b_gate = (const float*)d_in[4];
    const float* W_out  = (const float*)d_in[5];
    const float* b_out  = (const float*)d_in[6];
    const float* A_log  = (const float*)d_in[7];
    const float* B_mat  = (const float*)d_in[8];
    const float* C_mat  = (const float*)d_in[9];
    const float* D_vec  = (const float*)d_in[10];
    float* out = (float*)d_out;

    cudaFuncSetAttribute(gemm_mma<0>, cudaFuncAttributeMaxDynamicSharedMemorySize, SMEM_TOTAL);
    cudaFuncSetAttribute(gemm_mma<1>, cudaFuncAttributeMaxDynamicSharedMemorySize, SMEM_TOTAL);
    cudaFuncSetAttribute(gemm_mma<2>, cudaFuncAttributeMaxDynamicSharedMemorySize, SMEM_TOTAL);

    __nv_bfloat16 *xh, *xl, *winh, *winl, *wgh, *wgl, *woh, *wol, *gsh, *gsl;
    cudaGetSymbolAddress((void**)&xh,   g_x_hi);   cudaGetSymbolAddress((void**)&xl,   g_x_lo);
    cudaGetSymbolAddress((void**)&winh, g_win_hi); cudaGetSymbolAddress((void**)&winl, g_win_lo);
    cudaGetSymbolAddress((void**)&wgh,  g_wg_hi);  cudaGetSymbolAddress((void**)&wgl,  g_wg_lo);
    cudaGetSymbolAddress((void**)&woh,  g_wo_hi);  cudaGetSymbolAddress((void**)&wol,  g_wo_lo);
    cudaGetSymbolAddress((void**)&gsh,  g_gss_hi); cudaGetSymbolAddress((void**)&gsl,  g_gss_lo);

    // 1) split fp32 inputs to bf16 hi/lo
    split_kernel<<<(TOK * DMODEL) / 256, 256>>>(x, xh, xl, TOK * DMODEL);
    split_kernel<<<(2 * DINNER * DMODEL) / 256, 256>>>(W_in, winh, winl, 2 * DINNER * DMODEL);
    split_kernel<<<(DINNER * DMODEL) / 256, 256>>>(W_gate, wgh, wgl, DINNER * DMODEL);
    split_kernel<<<(DMODEL * DINNER) / 256, 256>>>(W_out, woh, wol, DMODEL * DINNER);

    // 2) proj = x @ W_in^T + b_in  -> x_proj | relu(delta)
    gemm_mma<0><<<dim3(4096 / 128, TOK / 128), 256, SMEM_TOTAL>>>(
        xh, xl, winh, winl, b_in, nullptr, 2 * DINNER, DMODEL);
    // 3) gate = sigmoid(x @ W_gate^T + b_gate)
    gemm_mma<1><<<dim3(2048 / 128, TOK / 128), 256, SMEM_TOTAL>>>(
        xh, xl, wgh, wgl, b_gate, nullptr, DINNER, DMODEL);

    // 4) selective scan -> g_gss (bf16 split)
    scan_kernel<<<(NBATCH * DINNER * DSTATE) / 256, 256>>>(A_log, B_mat, C_mat, D_vec);

    // 5) out = gss @ W_out^T + b_out
    gemm_mma<2><<<dim3(1024 / 128, TOK / 128), 256, SMEM_TOTAL>>>(
        gsh, gsl, woh, wol, b_out, out, DMODEL, DINNER);
}

// round 4
// speedup vs baseline: 1.4742x; 1.0421x over previous
#include <cuda_runtime.h>
#include <cuda_bf16.h>
#include <cstdint>

// Problem constants
#define TOK     2048      // B*S
#define DMODEL  1024
#define DINNER  2048
#define DSTATE  16
#define SEQLEN  1024
#define NBATCH  2
#define NIN     (3 * DINNER)   // 6144 fused output cols (4096 proj + 2048 gate)

// ---------------------------------------------------------------------------
// Device-global scratch
// ---------------------------------------------------------------------------
__device__ float g_xproj[TOK * DINNER];
__device__ float g_delta[TOK * DINNER];
__device__ float g_gate [TOK * DINNER];

__device__ __nv_bfloat16 g_x_hi [TOK * DMODEL],     g_x_lo [TOK * DMODEL];
__device__ __nv_bfloat16 g_wi_hi[NIN * DMODEL],     g_wi_lo[NIN * DMODEL];   // W_in ++ W_gate
__device__ __nv_bfloat16 g_wo_hi[DMODEL * DINNER],  g_wo_lo[DMODEL * DINNER];
__device__ __nv_bfloat16 g_gss_hi[TOK * DINNER],    g_gss_lo[TOK * DINNER];

// ---------------------------------------------------------------------------
// PTX helpers (base-target-safe: cp.async / ldmatrix / mma.sync)
// ---------------------------------------------------------------------------
__device__ __forceinline__ uint32_t smem_u32(const void* p) {
    uint32_t a;
    asm("{ .reg .u64 t; cvta.to.shared.u64 t, %1; cvt.u32.u64 %0, t; }" : "=r"(a) : "l"(p));
    return a;
}
__device__ __forceinline__ void cpa16(uint32_t s, const void* g) {
    asm volatile("cp.async.cg.shared.global [%0], [%1], 16;" :: "r"(s), "l"(g) : "memory");
}
__device__ __forceinline__ void cpa_commit() {
    asm volatile("cp.async.commit_group;" ::: "memory");
}
template <int N>
__device__ __forceinline__ void cpa_wait() {
    asm volatile("cp.async.wait_group %0;" :: "n"(N) : "memory");
}
__device__ __forceinline__ void ldsm4(uint32_t& r0, uint32_t& r1, uint32_t& r2,
                                      uint32_t& r3, uint32_t a) {
    asm volatile("ldmatrix.sync.aligned.m8n8.x4.shared.b16 {%0,%1,%2,%3}, [%4];"
                 : "=r"(r0), "=r"(r1), "=r"(r2), "=r"(r3) : "r"(a));
}
__device__ __forceinline__ void mma16816(float* d, const uint32_t* a, const uint32_t* b) {
    asm volatile(
        "mma.sync.aligned.m16n8k16.row.col.f32.bf16.bf16.f32 "
        "{%0,%1,%2,%3}, {%4,%5,%6,%7}, {%8,%9}, {%0,%1,%2,%3};"
        : "+f"(d[0]), "+f"(d[1]), "+f"(d[2]), "+f"(d[3])
        : "r"(a[0]), "r"(a[1]), "r"(a[2]), "r"(a[3]), "r"(b[0]), "r"(b[1]));
}

// Fast exp on the FMA/ALU pipes (no MUFU). Cody-Waite + deg-6 Taylor.
// Accurate to ~1e-7 rel for |z| < ~80.
__device__ __forceinline__ float fexp(float z) {
    float nf = rintf(z * 1.4426950408889634f);
    float r  = fmaf(nf, -0.693145751953125f, z);     // ln2_hi
    r        = fmaf(nf, -1.42860677e-6f, r);         // ln2_lo
    float p  = 1.0f / 720.0f;
    p = fmaf(p, r, 1.0f / 120.0f);
    p = fmaf(p, r, 1.0f / 24.0f);
    p = fmaf(p, r, 1.0f / 6.0f);
    p = fmaf(p, r, 0.5f);
    p = fmaf(p, r, 1.0f);
    p = fmaf(p, r, 1.0f);
    float s = __int_as_float(((int)nf + 127) << 23);
    return p * s;
}

// ---------------------------------------------------------------------------
// SMEM layout: 2 stages x (A_hi|A_lo|B_hi|B_lo), 128 rows x 80B padded
// ---------------------------------------------------------------------------
#define ROWB        80
#define TILE_B      (128 * ROWB)
#define STAGE_B     (4 * TILE_B)
#define SM_BIAS_OFF (2 * STAGE_B)
#define SMEM_TOTAL  (SM_BIAS_OFF + 512)

__device__ __forceinline__ void tile_cpasync(const __nv_bfloat16* __restrict__ g,
                                             int rowBase, int kt, int ld,
                                             uint32_t sdst, int tid) {
#pragma unroll
    for (int i = 0; i < 2; i++) {
        int seg = tid + i * 256;
        int r   = seg >> 2;
        int c   = seg & 3;
        cpa16(sdst + r * ROWB + c * 16,
              g + (size_t)(rowBase + r) * ld + kt + c * 8);
    }
}

// ---------------------------------------------------------------------------
// Split-bf16 tensor-core GEMM:  C[m,n] = sum_k A[m,k]*W[n,k] + bias[n]
// EPI 0 (fused in-proj): N=6144; col<2048 -> g_xproj, <4096 relu -> g_delta,
//                        else sigmoid -> g_gate. biasA=b_in, biasB=b_gate.
// EPI 2 (out-proj): +bias -> Cout
// ---------------------------------------------------------------------------
template <int EPI>
__global__ void __launch_bounds__(256, 2)
gemm_mma(const __nv_bfloat16* __restrict__ Ah, const __nv_bfloat16* __restrict__ Al,
         const __nv_bfloat16* __restrict__ Wh, const __nv_bfloat16* __restrict__ Wl,
         const float* __restrict__ biasA, const float* __restrict__ biasB,
         float* __restrict__ Cout, int N, int K)
{
    extern __shared__ char smem[];
    uint32_t sbase = smem_u32(smem);

    const int tid = threadIdx.x;
    const int wid = tid >> 5;
    const int l   = tid & 31;
    const int wm  = wid >> 2;
    const int wn  = wid & 3;
    const int mo  = wm * 64;
    const int no  = wn * 32;

    const int rowBase = blockIdx.y * 128;
    const int colBase = blockIdx.x * 128;

    if (tid < 128) {
        float bv;
        if (EPI == 0)
            bv = (colBase < 2 * DINNER) ? biasA[colBase + tid]
                                        : biasB[colBase - 2 * DINNER + tid];
        else
            bv = biasA[colBase + tid];
        *reinterpret_cast<float*>(smem + SM_BIAS_OFF + tid * 4) = bv;
    }

    const uint32_t aRow = (uint32_t)((mo + (l & 15)) * ROWB + ((l >> 4) * 16));
    const uint32_t bRow = (uint32_t)((no + (l & 7) + ((l & 16) ? 8 : 0)) * ROWB
                                     + (((l >> 3) & 1) * 16));

    float acc[4][4][4];
#pragma unroll
    for (int mi = 0; mi < 4; mi++)
#pragma unroll
        for (int ni = 0; ni < 4; ni++)
#pragma unroll
            for (int r = 0; r < 4; r++) acc[mi][ni][r] = 0.0f;

    const int NC = K / 32;

    {
        uint32_t st = sbase;
        tile_cpasync(Ah, rowBase, 0, K, st,              tid);
        tile_cpasync(Al, rowBase, 0, K, st + TILE_B,     tid);
        tile_cpasync(Wh, colBase, 0, K, st + 2 * TILE_B, tid);
        tile_cpasync(Wl, colBase, 0, K, st + 3 * TILE_B, tid);
        cpa_commit();
    }

    for (int c = 0; c < NC; c++) {
        if (c + 1 < NC) {
            uint32_t st = sbase + ((c + 1) & 1) * STAGE_B;
            int kt = (c + 1) * 32;
            tile_cpasync(Ah, rowBase, kt, K, st,              tid);
            tile_cpasync(Al, rowBase, kt, K, st + TILE_B,     tid);
            tile_cpasync(Wh, colBase, kt, K, st + 2 * TILE_B, tid);
            tile_cpasync(Wl, colBase, kt, K, st + 3 * TILE_B, tid);
            cpa_commit();
            cpa_wait<1>();
        } else {
            cpa_wait<0>();
        }
        __syncthreads();

        uint32_t st = sbase + (c & 1) * STAGE_B;
#pragma unroll
        for (int ks = 0; ks < 2; ks++) {
            uint32_t ah[4][4], al[4][4], bh[8], bl[8];
#pragma unroll
            for (int mi = 0; mi < 4; mi++) {
                uint32_t ad = st + aRow + mi * (16 * ROWB) + ks * 32;
                ldsm4(ah[mi][0], ah[mi][1], ah[mi][2], ah[mi][3], ad);
                ldsm4(al[mi][0], al[mi][1], al[mi][2], al[mi][3], ad + TILE_B);
            }
#pragma unroll
            for (int np = 0; np < 2; np++) {
                uint32_t bd = st + 2 * TILE_B + bRow + np * (16 * ROWB) + ks * 32;
                ldsm4(bh[np * 4 + 0], bh[np * 4 + 1], bh[np * 4 + 2], bh[np * 4 + 3], bd);
                ldsm4(bl[np * 4 + 0], bl[np * 4 + 1], bl[np * 4 + 2], bl[np * 4 + 3],
                      bd + TILE_B);
            }
#pragma unroll
            for (int mi = 0; mi < 4; mi++)
#pragma unroll
                for (int ni = 0; ni < 4; ni++) {
                    mma16816(acc[mi][ni], ah[mi], &bh[ni * 2]);
                    mma16816(acc[mi][ni], ah[mi], &bl[ni * 2]);
                    mma16816(acc[mi][ni], al[mi], &bh[ni * 2]);
                }
        }
        __syncthreads();
    }

    const float* sb = reinterpret_cast<const float*>(smem + SM_BIAS_OFF);
    const int g  = l >> 2;
    const int t4 = l & 3;
#pragma unroll
    for (int mi = 0; mi < 4; mi++) {
#pragma unroll
        for (int ni = 0; ni < 4; ni++) {
            int bc   = no + ni * 8 + 2 * t4;
            int col  = colBase + bc;
            int row0 = rowBase + mo + mi * 16 + g;
            int row1 = row0 + 8;
            float2 v0, v1;
            v0.x = acc[mi][ni][0] + sb[bc];
            v0.y = acc[mi][ni][1] + sb[bc + 1];
            v1.x = acc[mi][ni][2] + sb[bc];
            v1.y = acc[mi][ni][3] + sb[bc + 1];
            if (EPI == 0) {
                if (colBase < DINNER) {
                    *reinterpret_cast<float2*>(&g_xproj[(size_t)row0 * DINNER + col]) = v0;
                    *reinterpret_cast<float2*>(&g_xproj[(size_t)row1 * DINNER + col]) = v1;
                } else if (colBase < 2 * DINNER) {
                    v0.x = fmaxf(v0.x, 0.f); v0.y = fmaxf(v0.y, 0.f);
                    v1.x = fmaxf(v1.x, 0.f); v1.y = fmaxf(v1.y, 0.f);
                    int cc = col - DINNER;
                    *reinterpret_cast<float2*>(&g_delta[(size_t)row0 * DINNER + cc]) = v0;
                    *reinterpret_cast<float2*>(&g_delta[(size_t)row1 * DINNER + cc]) = v1;
                } else {
                    v0.x = 1.f / (1.f + fexp(-v0.x));
                    v0.y = 1.f / (1.f + fexp(-v0.y));
                    v1.x = 1.f / (1.f + fexp(-v1.x));
                    v1.y = 1.f / (1.f + fexp(-v1.y));
                    int cc = col - 2 * DINNER;
                    *reinterpret_cast<float2*>(&g_gate[(size_t)row0 * DINNER + cc]) = v0;
                    *reinterpret_cast<float2*>(&g_gate[(size_t)row1 * DINNER + cc]) = v1;
                }
            } else {
                *reinterpret_cast<float2*>(&Cout[(size_t)row0 * N + col]) = v0;
                *reinterpret_cast<float2*>(&Cout[(size_t)row1 * N + col]) = v1;
            }
        }
    }
}

// ---------------------------------------------------------------------------
// Vectorized fp32 -> bf16 hi/lo split: 8 elems / thread
// ---------------------------------------------------------------------------
__global__ void __launch_bounds__(256)
split8_kernel(const float4* __restrict__ src, uint4* __restrict__ hi,
              uint4* __restrict__ lo, int n8)
{
    int i = blockIdx.x * blockDim.x + threadIdx.x;
    if (i >= n8) return;
    float4 u = src[2 * i];
    float4 v = src[2 * i + 1];
    float f[8] = {u.x, u.y, u.z, u.w, v.x, v.y, v.z, v.w};
    uint16_t hb[8], lb[8];
#pragma unroll
    for (int k = 0; k < 8; k++) {
        __nv_bfloat16 h = __float2bfloat16(f[k]);
        float r = f[k] - __bfloat162float(h);
        __nv_bfloat16 lw = __float2bfloat16(r);
        hb[k] = *reinterpret_cast<uint16_t*>(&h);
        lb[k] = *reinterpret_cast<uint16_t*>(&lw);
    }
    uint4 ho, lo4;
    ho.x = hb[0] | ((uint32_t)hb[1] << 16);  ho.y = hb[2] | ((uint32_t)hb[3] << 16);
    ho.z = hb[4] | ((uint32_t)hb[5] << 16);  ho.w = hb[6] | ((uint32_t)hb[7] << 16);
    lo4.x = lb[0] | ((uint32_t)lb[1] << 16); lo4.y = lb[2] | ((uint32_t)lb[3] << 16);
    lo4.z = lb[4] | ((uint32_t)lb[5] << 16); lo4.w = lb[6] | ((uint32_t)lb[7] << 16);
    hi[i] = ho;
    lo[i] = lo4;
}

// ---------------------------------------------------------------------------
// Selective scan. One thread per (batch, channel, state); 16-lane groups.
// All exp on FMA pipe via fexp().
// ---------------------------------------------------------------------------
__global__ void __launch_bounds__(256)
scan_kernel(const float* __restrict__ A_log, const float* __restrict__ B_mat,
            const float* __restrict__ C_mat, const float* __restrict__ D_vec)
{
    int slot = blockIdx.x * (blockDim.x >> 4) + (threadIdx.x >> 4);
    int s    = threadIdx.x & 15;
    int b    = slot >> 11;
    int ch   = slot & (DINNER - 1);

    float As  = -fexp(A_log[ch * DSTATE + s]);
    float Bs  = B_mat[ch * DSTATE + s];
    float cs  = C_mat[s];
    float Dch = D_vec[ch];

    float h = 0.0f;
    size_t base = (size_t)b * SEQLEN * DINNER + ch;

#pragma unroll 4
    for (int t = 0; t < SEQLEN; t++) {
        size_t idx = base + (size_t)t * DINNER;
        float dt = g_delta[idx];
        float xt = g_xproj[idx];
        float a  = fexp(As * dt);
        h = fmaf(h, a, (xt * dt) * Bs);
        float p = h * cs;
        p += __shfl_xor_sync(0xffffffffu, p, 1);
        p += __shfl_xor_sync(0xffffffffu, p, 2);
        p += __shfl_xor_sync(0xffffffffu, p, 4);
        p += __shfl_xor_sync(0xffffffffu, p, 8);
        if (s == 0) {
            float v = g_gate[idx] * (p + xt * Dch);
            __nv_bfloat16 vh = __float2bfloat16(v);
            g_gss_hi[idx] = vh;
            g_gss_lo[idx] = __float2bfloat16(v - __bfloat162float(vh));
        }
    }
}

// ---------------------------------------------------------------------------
extern "C" void kernel_launch(void* const* d_in, const int* in_sizes, int n_in,
                              void* d_out, int out_size)
{
    const float* x      = (const float*)d_in[0];
    const float* W_in   = (const float*)d_in[1];
    const float* b_in   = (const float*)d_in[2];
    const float* W_gate = (const float*)d_in[3];
    const float* b_gate = (const float*)d_in[4];
    const float* W_out  = (const float*)d_in[5];
    const float* b_out  = (const float*)d_in[6];
    const float* A_log  = (const float*)d_in[7];
    const float* B_mat  = (const float*)d_in[8];
    const float* C_mat  = (const float*)d_in[9];
    const float* D_vec  = (const float*)d_in[10];
    float* out = (float*)d_out;

    cudaFuncSetAttribute(gemm_mma<0>, cudaFuncAttributeMaxDynamicSharedMemorySize, SMEM_TOTAL);
    cudaFuncSetAttribute(gemm_mma<2>, cudaFuncAttributeMaxDynamicSharedMemorySize, SMEM_TOTAL);

    __nv_bfloat16 *xh, *xl, *wih, *wil, *woh, *wol, *gsh, *gsl;
    cudaGetSymbolAddress((void**)&xh,  g_x_hi);  cudaGetSymbolAddress((void**)&xl,  g_x_lo);
    cudaGetSymbolAddress((void**)&wih, g_wi_hi); cudaGetSymbolAddress((void**)&wil, g_wi_lo);
    cudaGetSymbolAddress((void**)&woh, g_wo_hi); cudaGetSymbolAddress((void**)&wol, g_wo_lo);
    cudaGetSymbolAddress((void**)&gsh, g_gss_hi); cudaGetSymbolAddress((void**)&gsl, g_gss_lo);

    const size_t WG_OFF = (size_t)2 * DINNER * DMODEL;   // W_gate offset in combined array

    // 1) splits (vectorized, 8 elems/thread)
    {
        int n;
        n = TOK * DMODEL;
        split8_kernel<<<(n / 8 + 255) / 256, 256>>>((const float4*)x, (uint4*)xh, (uint4*)xl, n / 8);
        n = 2 * DINNER * DMODEL;
        split8_kernel<<<(n / 8 + 255) / 256, 256>>>((const float4*)W_in, (uint4*)wih, (uint4*)wil, n / 8);
        n = DINNER * DMODEL;
        split8_kernel<<<(n / 8 + 255) / 256, 256>>>((const float4*)W_gate,
                                                    (uint4*)(wih + WG_OFF), (uint4*)(wil + WG_OFF), n / 8);
        n = DMODEL * DINNER;
        split8_kernel<<<(n / 8 + 255) / 256, 256>>>((const float4*)W_out, (uint4*)woh, (uint4*)wol, n / 8);
    }

    // 2) fused in-proj + gate GEMM (N = 6144)
    gemm_mma<0><<<dim3(NIN / 128, TOK / 128), 256, SMEM_TOTAL>>>(
        xh, xl, wih, wil, b_in, b_gate, nullptr, NIN, DMODEL);

    // 3) selective scan -> g_gss (bf16 split)
    scan_kernel<<<(NBATCH * DINNER * DSTATE) / 256, 256>>>(A_log, B_mat, C_mat, D_vec);

    // 4) out = gss @ W_out^T + b_out
    gemm_mma<2><<<dim3(DMODEL / 128, TOK / 128), 256, SMEM_TOTAL>>>(
        gsh, gsl, woh, wol, b_out, nullptr, out, DMODEL, DINNER);
}

// round 5
// speedup vs baseline: 2.5669x; 1.7412x over previous
#include <cuda_runtime.h>
#include <cuda_bf16.h>
#include <cstdint>

// Problem constants
#define TOK     2048      // B*S
#define DMODEL  1024
#define DINNER  2048
#define DSTATE  16
#define SEQLEN  1024
#define NBATCH  2
#define NIN     (3 * DINNER)   // 6144 fused output cols
#define CHK     16             // scan chunks
#define CHL     (SEQLEN / CHK) // 64 steps per chunk
#define NSLOT   (NBATCH * DINNER)            // 4096
#define NSS     (NSLOT * DSTATE)             // 65536

// ---------------------------------------------------------------------------
// Device-global scratch
// ---------------------------------------------------------------------------
__device__ float g_xproj[TOK * DINNER];
__device__ float g_delta[TOK * DINNER];
__device__ float g_gate [TOK * DINNER];

__device__ float g_P [CHK * NSS];   // chunk A-products
__device__ float g_q [CHK * NSS];   // chunk local states
__device__ float g_h0[CHK * NSS];   // chunk initial states

__device__ __nv_bfloat16 g_x_hi [TOK * DMODEL],     g_x_lo [TOK * DMODEL];
__device__ __nv_bfloat16 g_wi_hi[NIN * DMODEL],     g_wi_lo[NIN * DMODEL];
__device__ __nv_bfloat16 g_wo_hi[DMODEL * DINNER],  g_wo_lo[DMODEL * DINNER];
__device__ __nv_bfloat16 g_gss_hi[TOK * DINNER],    g_gss_lo[TOK * DINNER];

// ---------------------------------------------------------------------------
// PTX helpers
// ---------------------------------------------------------------------------
__device__ __forceinline__ uint32_t smem_u32(const void* p) {
    uint32_t a;
    asm("{ .reg .u64 t; cvta.to.shared.u64 t, %1; cvt.u32.u64 %0, t; }" : "=r"(a) : "l"(p));
    return a;
}
__device__ __forceinline__ void cpa16(uint32_t s, const void* g) {
    asm volatile("cp.async.cg.shared.global [%0], [%1], 16;" :: "r"(s), "l"(g) : "memory");
}
__device__ __forceinline__ void cpa_commit() {
    asm volatile("cp.async.commit_group;" ::: "memory");
}
template <int N>
__device__ __forceinline__ void cpa_wait() {
    asm volatile("cp.async.wait_group %0;" :: "n"(N) : "memory");
}
__device__ __forceinline__ void ldsm4(uint32_t& r0, uint32_t& r1, uint32_t& r2,
                                      uint32_t& r3, uint32_t a) {
    asm volatile("ldmatrix.sync.aligned.m8n8.x4.shared.b16 {%0,%1,%2,%3}, [%4];"
                 : "=r"(r0), "=r"(r1), "=r"(r2), "=r"(r3) : "r"(a));
}
__device__ __forceinline__ void mma16816(float* d, const uint32_t* a, const uint32_t* b) {
    asm volatile(
        "mma.sync.aligned.m16n8k16.row.col.f32.bf16.bf16.f32 "
        "{%0,%1,%2,%3}, {%4,%5,%6,%7}, {%8,%9}, {%0,%1,%2,%3};"
        : "+f"(d[0]), "+f"(d[1]), "+f"(d[2]), "+f"(d[3])
        : "r"(a[0]), "r"(a[1]), "r"(a[2]), "r"(a[3]), "r"(b[0]), "r"(b[1]));
}

// Fast exp on FMA/ALU pipes (Cody-Waite + deg-6), ~1e-7 rel.
__device__ __forceinline__ float fexp(float z) {
    float nf = rintf(z * 1.4426950408889634f);
    float r  = fmaf(nf, -0.693145751953125f, z);
    r        = fmaf(nf, -1.42860677e-6f, r);
    float p  = 1.0f / 720.0f;
    p = fmaf(p, r, 1.0f / 120.0f);
    p = fmaf(p, r, 1.0f / 24.0f);
    p = fmaf(p, r, 1.0f / 6.0f);
    p = fmaf(p, r, 0.5f);
    p = fmaf(p, r, 1.0f);
    p = fmaf(p, r, 1.0f);
    float s = __int_as_float(((int)nf + 127) << 23);
    return p * s;
}

// ---------------------------------------------------------------------------
// SMEM geometry (per-BM): stage = Ah|Al (BM rows) ++ Bh|Bl (128 rows), 80B rows
// ---------------------------------------------------------------------------
#define ROWB 80
#define SMEMT(BM) (2 * (2 * (BM) * ROWB + 2 * 128 * ROWB) + 512)

template <int ROWS>
__device__ __forceinline__ void tile_cpasync(const __nv_bfloat16* __restrict__ g,
                                             int rowBase, int kt, int ld,
                                             uint32_t sdst, int tid) {
#pragma unroll
    for (int i = 0; i < ROWS / 64; i++) {
        int seg = tid + i * 256;
        int r   = seg >> 2;
        int c   = seg & 3;
        cpa16(sdst + r * ROWB + c * 16,
              g + (size_t)(rowBase + r) * ld + kt + c * 8);
    }
}

// ---------------------------------------------------------------------------
// Split-bf16 tensor-core GEMM:  C[m,n] = sum_k A[m,k]*W[n,k] + bias[n]
// EPI 0 (fused in-proj, N=6144): xproj | relu->delta | sigmoid->gate
// EPI 2 (out-proj): +bias -> Cout
// BM: 128 or 64 (BN fixed 128, BK=32, 8 warps 2x4)
// ---------------------------------------------------------------------------
template <int EPI, int BM>
__global__ void __launch_bounds__(256, 2)
gemm_mma(const __nv_bfloat16* __restrict__ Ah, const __nv_bfloat16* __restrict__ Al,
         const __nv_bfloat16* __restrict__ Wh, const __nv_bfloat16* __restrict__ Wl,
         const float* __restrict__ biasA, const float* __restrict__ biasB,
         float* __restrict__ Cout, int N, int K)
{
    constexpr int MI     = BM / 32;           // per-warp 16-row tiles
    constexpr int ATILE  = BM * ROWB;
    constexpr int BTILE  = 128 * ROWB;
    constexpr int STAGE  = 2 * ATILE + 2 * BTILE;
    constexpr int BIASOF = 2 * STAGE;

    extern __shared__ char smem[];
    uint32_t sbase = smem_u32(smem);

    const int tid = threadIdx.x;
    const int wid = tid >> 5;
    const int l   = tid & 31;
    const int wm  = wid >> 2;
    const int wn  = wid & 3;
    const int mo  = wm * (BM / 2);
    const int no  = wn * 32;

    const int rowBase = blockIdx.y * BM;
    const int colBase = blockIdx.x * 128;

    if (tid < 128) {
        float bv;
        if (EPI == 0)
            bv = (colBase < 2 * DINNER) ? biasA[colBase + tid]
                                        : biasB[colBase - 2 * DINNER + tid];
        else
            bv = biasA[colBase + tid];
        *reinterpret_cast<float*>(smem + BIASOF + tid * 4) = bv;
    }

    const uint32_t aRow = (uint32_t)((mo + (l & 15)) * ROWB + ((l >> 4) * 16));
    const uint32_t bRow = (uint32_t)((no + (l & 7) + ((l & 16) ? 8 : 0)) * ROWB
                                     + (((l >> 3) & 1) * 16));

    float acc[MI][4][4];
#pragma unroll
    for (int mi = 0; mi < MI; mi++)
#pragma unroll
        for (int ni = 0; ni < 4; ni++)
#pragma unroll
            for (int r = 0; r < 4; r++) acc[mi][ni][r] = 0.0f;

    const int NC = K / 32;

    {
        uint32_t st = sbase;
        tile_cpasync<BM >(Ah, rowBase, 0, K, st,             tid);
        tile_cpasync<BM >(Al, rowBase, 0, K, st + ATILE,     tid);
        tile_cpasync<128>(Wh, colBase, 0, K, st + 2 * ATILE, tid);
        tile_cpasync<128>(Wl, colBase, 0, K, st + 2 * ATILE + BTILE, tid);
        cpa_commit();
    }

    for (int c = 0; c < NC; c++) {
        if (c + 1 < NC) {
            uint32_t st = sbase + ((c + 1) & 1) * STAGE;
            int kt = (c + 1) * 32;
            tile_cpasync<BM >(Ah, rowBase, kt, K, st,             tid);
            tile_cpasync<BM >(Al, rowBase, kt, K, st + ATILE,     tid);
            tile_cpasync<128>(Wh, colBase, kt, K, st + 2 * ATILE, tid);
            tile_cpasync<128>(Wl, colBase, kt, K, st + 2 * ATILE + BTILE, tid);
            cpa_commit();
            cpa_wait<1>();
        } else {
            cpa_wait<0>();
        }
        __syncthreads();

        uint32_t st = sbase + (c & 1) * STAGE;
#pragma unroll
        for (int ks = 0; ks < 2; ks++) {
            uint32_t ah[MI][4], al[MI][4], bh[8], bl[8];
#pragma unroll
            for (int mi = 0; mi < MI; mi++) {
                uint32_t ad = st + aRow + mi * (16 * ROWB) + ks * 32;
                ldsm4(ah[mi][0], ah[mi][1], ah[mi][2], ah[mi][3], ad);
                ldsm4(al[mi][0], al[mi][1], al[mi][2], al[mi][3], ad + ATILE);
            }
#pragma unroll
            for (int np = 0; np < 2; np++) {
                uint32_t bd = st + 2 * ATILE + bRow + np * (16 * ROWB) + ks * 32;
                ldsm4(bh[np * 4 + 0], bh[np * 4 + 1], bh[np * 4 + 2], bh[np * 4 + 3], bd);
                ldsm4(bl[np * 4 + 0], bl[np * 4 + 1], bl[np * 4 + 2], bl[np * 4 + 3],
                      bd + BTILE);
            }
#pragma unroll
            for (int mi = 0; mi < MI; mi++)
#pragma unroll
                for (int ni = 0; ni < 4; ni++) {
                    mma16816(acc[mi][ni], ah[mi], &bh[ni * 2]);
                    mma16816(acc[mi][ni], ah[mi], &bl[ni * 2]);
                    mma16816(acc[mi][ni], al[mi], &bh[ni * 2]);
                }
        }
        __syncthreads();
    }

    const float* sb = reinterpret_cast<const float*>(smem + BIASOF);
    const int g  = l >> 2;
    const int t4 = l & 3;
#pragma unroll
    for (int mi = 0; mi < MI; mi++) {
#pragma unroll
        for (int ni = 0; ni < 4; ni++) {
            int bc   = no + ni * 8 + 2 * t4;
            int col  = colBase + bc;
            int row0 = rowBase + mo + mi * 16 + g;
            int row1 = row0 + 8;
            float2 v0, v1;
            v0.x = acc[mi][ni][0] + sb[bc];
            v0.y = acc[mi][ni][1] + sb[bc + 1];
            v1.x = acc[mi][ni][2] + sb[bc];
            v1.y = acc[mi][ni][3] + sb[bc + 1];
            if (EPI == 0) {
                if (colBase < DINNER) {
                    *reinterpret_cast<float2*>(&g_xproj[(size_t)row0 * DINNER + col]) = v0;
                    *reinterpret_cast<float2*>(&g_xproj[(size_t)row1 * DINNER + col]) = v1;
                } else if (colBase < 2 * DINNER) {
                    v0.x = fmaxf(v0.x, 0.f); v0.y = fmaxf(v0.y, 0.f);
                    v1.x = fmaxf(v1.x, 0.f); v1.y = fmaxf(v1.y, 0.f);
                    int cc = col - DINNER;
                    *reinterpret_cast<float2*>(&g_delta[(size_t)row0 * DINNER + cc]) = v0;
                    *reinterpret_cast<float2*>(&g_delta[(size_t)row1 * DINNER + cc]) = v1;
                } else {
                    v0.x = 1.f / (1.f + fexp(-v0.x));
                    v0.y = 1.f / (1.f + fexp(-v0.y));
                    v1.x = 1.f / (1.f + fexp(-v1.x));
                    v1.y = 1.f / (1.f + fexp(-v1.y));
                    int cc = col - 2 * DINNER;
                    *reinterpret_cast<float2*>(&g_gate[(size_t)row0 * DINNER + cc]) = v0;
                    *reinterpret_cast<float2*>(&g_gate[(size_t)row1 * DINNER + cc]) = v1;
                }
            } else {
                *reinterpret_cast<float2*>(&Cout[(size_t)row0 * N + col]) = v0;
                *reinterpret_cast<float2*>(&Cout[(size_t)row1 * N + col]) = v1;
            }
        }
    }
}

// ---------------------------------------------------------------------------
// Vectorized fp32 -> bf16 hi/lo split: 8 elems / thread
// ---------------------------------------------------------------------------
__global__ void __launch_bounds__(256)
split8_kernel(const float4* __restrict__ src, uint4* __restrict__ hi,
              uint4* __restrict__ lo, int n8)
{
    int i = blockIdx.x * blockDim.x + threadIdx.x;
    if (i >= n8) return;
    float4 u = src[2 * i];
    float4 v = src[2 * i + 1];
    float f[8] = {u.x, u.y, u.z, u.w, v.x, v.y, v.z, v.w};
    uint16_t hb[8], lb[8];
#pragma unroll
    for (int k = 0; k < 8; k++) {
        __nv_bfloat16 h = __float2bfloat16(f[k]);
        float r = f[k] - __bfloat162float(h);
        __nv_bfloat16 lw = __float2bfloat16(r);
        hb[k] = *reinterpret_cast<uint16_t*>(&h);
        lb[k] = *reinterpret_cast<uint16_t*>(&lw);
    }
    uint4 ho, lo4;
    ho.x = hb[0] | ((uint32_t)hb[1] << 16);  ho.y = hb[2] | ((uint32_t)hb[3] << 16);
    ho.z = hb[4] | ((uint32_t)hb[5] << 16);  ho.w = hb[6] | ((uint32_t)hb[7] << 16);
    lo4.x = lb[0] | ((uint32_t)lb[1] << 16); lo4.y = lb[2] | ((uint32_t)lb[3] << 16);
    lo4.z = lb[4] | ((uint32_t)lb[5] << 16); lo4.w = lb[6] | ((uint32_t)lb[7] << 16);
    hi[i] = ho;
    lo[i] = lo4;
}

// ---------------------------------------------------------------------------
// Chunked selective scan.
// Phase A: per (chunk, slot, state): P = prod a, q = local h (h_in = 0)
// Phase B: compose chunk-initial states h0
// Phase C: re-run each chunk from h0, reduce over states, gate, emit bf16 split
// ---------------------------------------------------------------------------
__global__ void __launch_bounds__(256)
scanA_kernel(const float* __restrict__ A_log, const float* __restrict__ B_mat)
{
    int gidx  = blockIdx.x * 16 + (threadIdx.x >> 4);   // 0..65535
    int s     = threadIdx.x & 15;
    int chunk = gidx >> 12;
    int slot  = gidx & (NSLOT - 1);
    int b     = slot >> 11;
    int ch    = slot & (DINNER - 1);

    float As = -fexp(A_log[ch * DSTATE + s]);
    float Bs = B_mat[ch * DSTATE + s];

    float P = 1.0f, q = 0.0f;
    size_t base = (size_t)b * SEQLEN * DINNER + (size_t)chunk * CHL * DINNER + ch;

#pragma unroll 4
    for (int t = 0; t < CHL; t++) {
        size_t idx = base + (size_t)t * DINNER;
        float dt = g_delta[idx];
        float xt = g_xproj[idx];
        float a  = fexp(As * dt);
        q = fmaf(q, a, (xt * dt) * Bs);
        P *= a;
    }
    g_P[(size_t)gidx * DSTATE + s] = P;
    g_q[(size_t)gidx * DSTATE + s] = q;
}

__global__ void __launch_bounds__(256)
scanB_kernel()
{
    int i = blockIdx.x * 256 + threadIdx.x;   // 0..65535 = slot*16 + s
    float h = 0.0f;
#pragma unroll
    for (int k = 0; k < CHK; k++) {
        g_h0[(size_t)k * NSS + i] = h;
        h = fmaf(g_P[(size_t)k * NSS + i], h, g_q[(size_t)k * NSS + i]);
    }
}

__global__ void __launch_bounds__(256)
scanC_kernel(const float* __restrict__ A_log, const float* __restrict__ B_mat,
             const float* __restrict__ C_mat, const float* __restrict__ D_vec)
{
    int gidx  = blockIdx.x * 16 + (threadIdx.x >> 4);
    int s     = threadIdx.x & 15;
    int chunk = gidx >> 12;
    int slot  = gidx & (NSLOT - 1);
    int b     = slot >> 11;
    int ch    = slot & (DINNER - 1);

    float As  = -fexp(A_log[ch * DSTATE + s]);
    float Bs  = B_mat[ch * DSTATE + s];
    float cs  = C_mat[s];
    float Dch = D_vec[ch];

    float h = g_h0[(size_t)gidx * DSTATE + s];
    size_t base = (size_t)b * SEQLEN * DINNER + (size_t)chunk * CHL * DINNER + ch;

#pragma unroll 4
    for (int t = 0; t < CHL; t++) {
        size_t idx = base + (size_t)t * DINNER;
        float dt = g_delta[idx];
        float xt = g_xproj[idx];
        float a  = fexp(As * dt);
        h = fmaf(h, a, (xt * dt) * Bs);
        float p = h * cs;
        p += __shfl_xor_sync(0xffffffffu, p, 1);
        p += __shfl_xor_sync(0xffffffffu, p, 2);
        p += __shfl_xor_sync(0xffffffffu, p, 4);
        p += __shfl_xor_sync(0xffffffffu, p, 8);
        if (s == 0) {
            float v = g_gate[idx] * (p + xt * Dch);
            __nv_bfloat16 vh = __float2bfloat16(v);
            g_gss_hi[idx] = vh;
            g_gss_lo[idx] = __float2bfloat16(v - __bfloat162float(vh));
        }
    }
}

// ---------------------------------------------------------------------------
extern "C" void kernel_launch(void* const* d_in, const int* in_sizes, int n_in,
                              void* d_out, int out_size)
{
    const float* x      = (const float*)d_in[0];
    const float* W_in   = (const float*)d_in[1];
    const float* b_in   = (const float*)d_in[2];
    const float* W_gate = (const float*)d_in[3];
    const float* b_gate = (const float*)d_in[4];
    const float* W_out  = (const float*)d_in[5];
    const float* b_out  = (const float*)d_in[6];
    const float* A_log  = (const float*)d_in[7];
    const float* B_mat  = (const float*)d_in[8];
    const float* C_mat  = (const float*)d_in[9];
    const float* D_vec  = (const float*)d_in[10];
    float* out = (float*)d_out;

    cudaFuncSetAttribute((const void*)gemm_mma<0, 128>,
                         cudaFuncAttributeMaxDynamicSharedMemorySize, SMEMT(128));
    cudaFuncSetAttribute((const void*)gemm_mma<2, 64>,
                         cudaFuncAttributeMaxDynamicSharedMemorySize, SMEMT(64));

    __nv_bfloat16 *xh, *xl, *wih, *wil, *woh, *wol, *gsh, *gsl;
    cudaGetSymbolAddress((void**)&xh,  g_x_hi);  cudaGetSymbolAddress((void**)&xl,  g_x_lo);
    cudaGetSymbolAddress((void**)&wih, g_wi_hi); cudaGetSymbolAddress((void**)&wil, g_wi_lo);
    cudaGetSymbolAddress((void**)&woh, g_wo_hi); cudaGetSymbolAddress((void**)&wol, g_wo_lo);
    cudaGetSymbolAddress((void**)&gsh, g_gss_hi); cudaGetSymbolAddress((void**)&gsl, g_gss_lo);

    const size_t WG_OFF = (size_t)2 * DINNER * DMODEL;

    // 1) fp32 -> bf16 hi/lo splits
    {
        int n;
        n = TOK * DMODEL;
        split8_kernel<<<(n / 8 + 255) / 256, 256>>>((const float4*)x, (uint4*)xh, (uint4*)xl, n / 8);
        n = 2 * DINNER * DMODEL;
        split8_kernel<<<(n / 8 + 255) / 256, 256>>>((const float4*)W_in, (uint4*)wih, (uint4*)wil, n / 8);
        n = DINNER * DMODEL;
        split8_kernel<<<(n / 8 + 255) / 256, 256>>>((const float4*)W_gate,
                                                    (uint4*)(wih + WG_OFF), (uint4*)(wil + WG_OFF), n / 8);
        n = DMODEL * DINNER;
        split8_kernel<<<(n / 8 + 255) / 256, 256>>>((const float4*)W_out, (uint4*)woh, (uint4*)wol, n / 8);
    }

    // 2) fused in-proj + gate GEMM (N = 6144)
    gemm_mma<0, 128><<<dim3(NIN / 128, TOK / 128), 256, SMEMT(128)>>>(
        xh, xl, wih, wil, b_in, b_gate, nullptr, NIN, DMODEL);

    // 3) chunked selective scan
    scanA_kernel<<<(CHK * NSS) / (16 * 256) * 16, 256>>>(A_log, B_mat);
    scanB_kernel<<<NSS / 256, 256>>>();
    scanC_kernel<<<(CHK * NSS) / (16 * 256) * 16, 256>>>(A_log, B_mat, C_mat, D_vec);

    // 4) out = gss @ W_out^T + b_out  (BM=64 tiles -> 256 CTAs)
    gemm_mma<2, 64><<<dim3(DMODEL / 128, TOK / 64), 256, SMEMT(64)>>>(
        gsh, gsl, woh, wol, b_out, nullptr, out, DMODEL, DINNER);
}

// round 6
// speedup vs baseline: 3.3483x; 1.3044x over previous
#include <cuda_runtime.h>
#include <cuda_fp16.h>
#include <cstdint>

// Problem constants
#define TOK     2048
#define DMODEL  1024
#define DINNER  2048
#define DSTATE  16
#define SEQLEN  1024
#define NBATCH  2
#define NIN     (3 * DINNER)   // 6144 fused cols
#define CHK     16
#define CHL     (SEQLEN / CHK)
#define NSLOT   (NBATCH * DINNER)
#define NSS     (NSLOT * DSTATE)

// ---------------------------------------------------------------------------
// Device-global scratch
// ---------------------------------------------------------------------------
__device__ float g_xproj[TOK * DINNER];
__device__ float g_delta[TOK * DINNER];
__device__ float g_gate [TOK * DINNER];

__device__ float g_P [CHK * NSS];
__device__ float g_q [CHK * NSS];
__device__ float g_h0[CHK * NSS];

__device__ __half g_x_hi [TOK * DMODEL], g_x_lo [TOK * DMODEL];
__device__ __half g_wi   [NIN * DMODEL];                 // W_in ++ W_gate, fp16
__device__ __half g_wo   [DMODEL * DINNER];              // W_out, fp16
__device__ __half g_gss_hi[TOK * DINNER], g_gss_lo[TOK * DINNER];

// ---------------------------------------------------------------------------
// PTX helpers
// ---------------------------------------------------------------------------
__device__ __forceinline__ uint32_t smem_u32(const void* p) {
    uint32_t a;
    asm("{ .reg .u64 t; cvta.to.shared.u64 t, %1; cvt.u32.u64 %0, t; }" : "=r"(a) : "l"(p));
    return a;
}
__device__ __forceinline__ void cpa16(uint32_t s, const void* g) {
    asm volatile("cp.async.cg.shared.global [%0], [%1], 16;" :: "r"(s), "l"(g) : "memory");
}
__device__ __forceinline__ void cpa_commit() {
    asm volatile("cp.async.commit_group;" ::: "memory");
}
template <int N>
__device__ __forceinline__ void cpa_wait() {
    asm volatile("cp.async.wait_group %0;" :: "n"(N) : "memory");
}
__device__ __forceinline__ void ldsm4(uint32_t& r0, uint32_t& r1, uint32_t& r2,
                                      uint32_t& r3, uint32_t a) {
    asm volatile("ldmatrix.sync.aligned.m8n8.x4.shared.b16 {%0,%1,%2,%3}, [%4];"
                 : "=r"(r0), "=r"(r1), "=r"(r2), "=r"(r3) : "r"(a));
}
__device__ __forceinline__ void mma16816(float* d, const uint32_t* a, const uint32_t* b) {
    asm volatile(
        "mma.sync.aligned.m16n8k16.row.col.f32.f16.f16.f32 "
        "{%0,%1,%2,%3}, {%4,%5,%6,%7}, {%8,%9}, {%0,%1,%2,%3};"
        : "+f"(d[0]), "+f"(d[1]), "+f"(d[2]), "+f"(d[3])
        : "r"(a[0]), "r"(a[1]), "r"(a[2]), "r"(a[3]), "r"(b[0]), "r"(b[1]));
}

// Fast exp on FMA/ALU pipes (used only in GEMM epilogue sigmoid)
__device__ __forceinline__ float fexp(float z) {
    float nf = rintf(z * 1.4426950408889634f);
    float r  = fmaf(nf, -0.693145751953125f, z);
    r        = fmaf(nf, -1.42860677e-6f, r);
    float p  = 1.0f / 720.0f;
    p = fmaf(p, r, 1.0f / 120.0f);
    p = fmaf(p, r, 1.0f / 24.0f);
    p = fmaf(p, r, 1.0f / 6.0f);
    p = fmaf(p, r, 0.5f);
    p = fmaf(p, r, 1.0f);
    p = fmaf(p, r, 1.0f);
    float s = __int_as_float(((int)nf + 127) << 23);
    return p * s;
}

// ---------------------------------------------------------------------------
// SMEM geometry: stage = Ah|Al (BM rows) ++ W (128 rows), 80B rows, 2 stages
// ---------------------------------------------------------------------------
#define ROWB 80
#define SMEMT(BM) (2 * (2 * (BM) * ROWB + 128 * ROWB) + 512)

template <int ROWS>
__device__ __forceinline__ void tile_cpasync(const __half* __restrict__ g,
                                             int rowBase, int kt, int ld,
                                             uint32_t sdst, int tid) {
#pragma unroll
    for (int i = 0; i < ROWS / 64; i++) {
        int seg = tid + i * 256;
        int r   = seg >> 2;
        int c   = seg & 3;
        cpa16(sdst + r * ROWB + c * 16,
              g + (size_t)(rowBase + r) * ld + kt + c * 8);
    }
}

// ---------------------------------------------------------------------------
// fp16 2-product GEMM: C = (Ah+Al) @ W^T + bias  (W single fp16)
// EPI 0 (N=6144): xproj | relu->delta | sigmoid->gate
// EPI 2: +bias -> Cout
// ---------------------------------------------------------------------------
template <int EPI, int BM>
__global__ void __launch_bounds__(256, 2)
gemm_mma(const __half* __restrict__ Ah, const __half* __restrict__ Al,
         const __half* __restrict__ W,
         const float* __restrict__ biasA, const float* __restrict__ biasB,
         float* __restrict__ Cout, int N, int K)
{
    constexpr int MI     = BM / 32;
    constexpr int ATILE  = BM * ROWB;
    constexpr int BTILE  = 128 * ROWB;
    constexpr int STAGE  = 2 * ATILE + BTILE;
    constexpr int BIASOF = 2 * STAGE;

    extern __shared__ char smem[];
    uint32_t sbase = smem_u32(smem);

    const int tid = threadIdx.x;
    const int wid = tid >> 5;
    const int l   = tid & 31;
    const int wm  = wid >> 2;
    const int wn  = wid & 3;
    const int mo  = wm * (BM / 2);
    const int no  = wn * 32;

    const int rowBase = blockIdx.y * BM;
    const int colBase = blockIdx.x * 128;

    if (tid < 128) {
        float bv;
        if (EPI == 0)
            bv = (colBase < 2 * DINNER) ? biasA[colBase + tid]
                                        : biasB[colBase - 2 * DINNER + tid];
        else
            bv = biasA[colBase + tid];
        *reinterpret_cast<float*>(smem + BIASOF + tid * 4) = bv;
    }

    const uint32_t aRow = (uint32_t)((mo + (l & 15)) * ROWB + ((l >> 4) * 16));
    const uint32_t bRow = (uint32_t)((no + (l & 7) + ((l & 16) ? 8 : 0)) * ROWB
                                     + (((l >> 3) & 1) * 16));

    float acc[MI][4][4];
#pragma unroll
    for (int mi = 0; mi < MI; mi++)
#pragma unroll
        for (int ni = 0; ni < 4; ni++)
#pragma unroll
            for (int r = 0; r < 4; r++) acc[mi][ni][r] = 0.0f;

    const int NC = K / 32;

    {
        uint32_t st = sbase;
        tile_cpasync<BM >(Ah, rowBase, 0, K, st,             tid);
        tile_cpasync<BM >(Al, rowBase, 0, K, st + ATILE,     tid);
        tile_cpasync<128>(W,  colBase, 0, K, st + 2 * ATILE, tid);
        cpa_commit();
    }

    for (int c = 0; c < NC; c++) {
        if (c + 1 < NC) {
            uint32_t st = sbase + ((c + 1) & 1) * STAGE;
            int kt = (c + 1) * 32;
            tile_cpasync<BM >(Ah, rowBase, kt, K, st,             tid);
            tile_cpasync<BM >(Al, rowBase, kt, K, st + ATILE,     tid);
            tile_cpasync<128>(W,  colBase, kt, K, st + 2 * ATILE, tid);
            cpa_commit();
            cpa_wait<1>();
        } else {
            cpa_wait<0>();
        }
        __syncthreads();

        uint32_t st = sbase + (c & 1) * STAGE;
#pragma unroll
        for (int ks = 0; ks < 2; ks++) {
            uint32_t ah[MI][4], al[MI][4], bh[8];
#pragma unroll
            for (int mi = 0; mi < MI; mi++) {
                uint32_t ad = st + aRow + mi * (16 * ROWB) + ks * 32;
                ldsm4(ah[mi][0], ah[mi][1], ah[mi][2], ah[mi][3], ad);
                ldsm4(al[mi][0], al[mi][1], al[mi][2], al[mi][3], ad + ATILE);
            }
#pragma unroll
            for (int np = 0; np < 2; np++) {
                uint32_t bd = st + 2 * ATILE + bRow + np * (16 * ROWB) + ks * 32;
                ldsm4(bh[np * 4 + 0], bh[np * 4 + 1], bh[np * 4 + 2], bh[np * 4 + 3], bd);
            }
#pragma unroll
            for (int mi = 0; mi < MI; mi++)
#pragma unroll
                for (int ni = 0; ni < 4; ni++) {
                    mma16816(acc[mi][ni], ah[mi], &bh[ni * 2]);
                    mma16816(acc[mi][ni], al[mi], &bh[ni * 2]);
                }
        }
        __syncthreads();
    }

    const float* sb = reinterpret_cast<const float*>(smem + BIASOF);
    const int g  = l >> 2;
    const int t4 = l & 3;
#pragma unroll
    for (int mi = 0; mi < MI; mi++) {
#pragma unroll
        for (int ni = 0; ni < 4; ni++) {
            int bc   = no + ni * 8 + 2 * t4;
            int col  = colBase + bc;
            int row0 = rowBase + mo + mi * 16 + g;
            int row1 = row0 + 8;
            float2 v0, v1;
            v0.x = acc[mi][ni][0] + sb[bc];
            v0.y = acc[mi][ni][1] + sb[bc + 1];
            v1.x = acc[mi][ni][2] + sb[bc];
            v1.y = acc[mi][ni][3] + sb[bc + 1];
            if (EPI == 0) {
                if (colBase < DINNER) {
                    *reinterpret_cast<float2*>(&g_xproj[(size_t)row0 * DINNER + col]) = v0;
                    *reinterpret_cast<float2*>(&g_xproj[(size_t)row1 * DINNER + col]) = v1;
                } else if (colBase < 2 * DINNER) {
                    v0.x = fmaxf(v0.x, 0.f); v0.y = fmaxf(v0.y, 0.f);
                    v1.x = fmaxf(v1.x, 0.f); v1.y = fmaxf(v1.y, 0.f);
                    int cc = col - DINNER;
                    *reinterpret_cast<float2*>(&g_delta[(size_t)row0 * DINNER + cc]) = v0;
                    *reinterpret_cast<float2*>(&g_delta[(size_t)row1 * DINNER + cc]) = v1;
                } else {
                    v0.x = 1.f / (1.f + fexp(-v0.x));
                    v0.y = 1.f / (1.f + fexp(-v0.y));
                    v1.x = 1.f / (1.f + fexp(-v1.x));
                    v1.y = 1.f / (1.f + fexp(-v1.y));
                    int cc = col - 2 * DINNER;
                    *reinterpret_cast<float2*>(&g_gate[(size_t)row0 * DINNER + cc]) = v0;
                    *reinterpret_cast<float2*>(&g_gate[(size_t)row1 * DINNER + cc]) = v1;
                }
            } else {
                *reinterpret_cast<float2*>(&Cout[(size_t)row0 * N + col]) = v0;
                *reinterpret_cast<float2*>(&Cout[(size_t)row1 * N + col]) = v1;
            }
        }
    }
}

// ---------------------------------------------------------------------------
// fp32 -> fp16 hi/lo split (8 elems / thread)
// ---------------------------------------------------------------------------
__global__ void __launch_bounds__(256)
split8h_kernel(const float4* __restrict__ src, uint4* __restrict__ hi,
               uint4* __restrict__ lo, int n8)
{
    int i = blockIdx.x * blockDim.x + threadIdx.x;
    if (i >= n8) return;
    float4 u = src[2 * i];
    float4 v = src[2 * i + 1];
    float f[8] = {u.x, u.y, u.z, u.w, v.x, v.y, v.z, v.w};
    uint16_t hb[8], lb[8];
#pragma unroll
    for (int k = 0; k < 8; k++) {
        __half h = __float2half(f[k]);
        float r = f[k] - __half2float(h);
        __half lw = __float2half(r);
        hb[k] = *reinterpret_cast<uint16_t*>(&h);
        lb[k] = *reinterpret_cast<uint16_t*>(&lw);
    }
    uint4 ho, lo4;
    ho.x = hb[0] | ((uint32_t)hb[1] << 16);  ho.y = hb[2] | ((uint32_t)hb[3] << 16);
    ho.z = hb[4] | ((uint32_t)hb[5] << 16);  ho.w = hb[6] | ((uint32_t)hb[7] << 16);
    lo4.x = lb[0] | ((uint32_t)lb[1] << 16); lo4.y = lb[2] | ((uint32_t)lb[3] << 16);
    lo4.z = lb[4] | ((uint32_t)lb[5] << 16); lo4.w = lb[6] | ((uint32_t)lb[7] << 16);
    hi[i] = ho;
    lo[i] = lo4;
}

// fp32 -> fp16 single convert (8 elems / thread)
__global__ void __launch_bounds__(256)
conv8_kernel(const float4* __restrict__ src, uint4* __restrict__ dst, int n8)
{
    int i = blockIdx.x * blockDim.x + threadIdx.x;
    if (i >= n8) return;
    float4 u = src[2 * i];
    float4 v = src[2 * i + 1];
    __half2 h0 = __floats2half2_rn(u.x, u.y);
    __half2 h1 = __floats2half2_rn(u.z, u.w);
    __half2 h2 = __floats2half2_rn(v.x, v.y);
    __half2 h3 = __floats2half2_rn(v.z, v.w);
    uint4 o;
    o.x = *reinterpret_cast<uint32_t*>(&h0);
    o.y = *reinterpret_cast<uint32_t*>(&h1);
    o.z = *reinterpret_cast<uint32_t*>(&h2);
    o.w = *reinterpret_cast<uint32_t*>(&h3);
    dst[i] = o;
}

// ---------------------------------------------------------------------------
// Chunked selective scan (exp via MUFU — issue-bound regime)
// ---------------------------------------------------------------------------
__global__ void __launch_bounds__(256)
scanA_kernel(const float* __restrict__ A_log, const float* __restrict__ B_mat)
{
    int gidx  = blockIdx.x * 16 + (threadIdx.x >> 4);
    int s     = threadIdx.x & 15;
    int chunk = gidx >> 12;
    int slot  = gidx & (NSLOT - 1);
    int b     = slot >> 11;
    int ch    = slot & (DINNER - 1);

    float As = -__expf(A_log[ch * DSTATE + s]);
    float Bs = B_mat[ch * DSTATE + s];

    float P = 1.0f, q = 0.0f;
    size_t base = (size_t)b * SEQLEN * DINNER + (size_t)chunk * CHL * DINNER + ch;

#pragma unroll 4
    for (int t = 0; t < CHL; t++) {
        size_t idx = base + (size_t)t * DINNER;
        float dt = g_delta[idx];
        float xt = g_xproj[idx];
        float a  = __expf(As * dt);
        q = fmaf(q, a, (xt * dt) * Bs);
        P *= a;
    }
    g_P[(size_t)gidx * DSTATE + s] = P;
    g_q[(size_t)gidx * DSTATE + s] = q;
}

__global__ void __launch_bounds__(256)
scanB_kernel()
{
    int i = blockIdx.x * 256 + threadIdx.x;
    float h = 0.0f;
#pragma unroll
    for (int k = 0; k < CHK; k++) {
        g_h0[(size_t)k * NSS + i] = h;
        h = fmaf(g_P[(size_t)k * NSS + i], h, g_q[(size_t)k * NSS + i]);
    }
}

__global__ void __launch_bounds__(256)
scanC_kernel(const float* __restrict__ A_log, const float* __restrict__ B_mat,
             const float* __restrict__ C_mat, const float* __restrict__ D_vec)
{
    int gidx  = blockIdx.x * 16 + (threadIdx.x >> 4);
    int s     = threadIdx.x & 15;
    int chunk = gidx >> 12;
    int slot  = gidx & (NSLOT - 1);
    int b     = slot >> 11;
    int ch    = slot & (DINNER - 1);

    float As  = -__expf(A_log[ch * DSTATE + s]);
    float Bs  = B_mat[ch * DSTATE + s];
    float cs  = C_mat[s];
    float Dch = D_vec[ch];

    float h = g_h0[(size_t)gidx * DSTATE + s];
    size_t base = (size_t)b * SEQLEN * DINNER + (size_t)chunk * CHL * DINNER + ch;

#pragma unroll 4
    for (int t = 0; t < CHL; t++) {
        size_t idx = base + (size_t)t * DINNER;
        float dt = g_delta[idx];
        float xt = g_xproj[idx];
        float a  = __expf(As * dt);
        h = fmaf(h, a, (xt * dt) * Bs);
        float p = h * cs;
        p += __shfl_xor_sync(0xffffffffu, p, 1);
        p += __shfl_xor_sync(0xffffffffu, p, 2);
        p += __shfl_xor_sync(0xffffffffu, p, 4);
        p += __shfl_xor_sync(0xffffffffu, p, 8);
        if (s == 0) {
            float v = g_gate[idx] * (p + xt * Dch);
            __half vh = __float2half(v);
            g_gss_hi[idx] = vh;
            g_gss_lo[idx] = __float2half(v - __half2float(vh));
        }
    }
}

// ---------------------------------------------------------------------------
extern "C" void kernel_launch(void* const* d_in, const int* in_sizes, int n_in,
                              void* d_out, int out_size)
{
    const float* x      = (const float*)d_in[0];
    const float* W_in   = (const float*)d_in[1];
    const float* b_in   = (const float*)d_in[2];
    const float* W_gate = (const float*)d_in[3];
    const float* b_gate = (const float*)d_in[4];
    const float* W_out  = (const float*)d_in[5];
    const float* b_out  = (const float*)d_in[6];
    const float* A_log  = (const float*)d_in[7];
    const float* B_mat  = (const float*)d_in[8];
    const float* C_mat  = (const float*)d_in[9];
    const float* D_vec  = (const float*)d_in[10];
    float* out = (float*)d_out;

    cudaFuncSetAttribute((const void*)gemm_mma<0, 128>,
                         cudaFuncAttributeMaxDynamicSharedMemorySize, SMEMT(128));
    cudaFuncSetAttribute((const void*)gemm_mma<2, 64>,
                         cudaFuncAttributeMaxDynamicSharedMemorySize, SMEMT(64));

    __half *xh, *xl, *wi, *wo, *gsh, *gsl;
    cudaGetSymbolAddress((void**)&xh,  g_x_hi);  cudaGetSymbolAddress((void**)&xl,  g_x_lo);
    cudaGetSymbolAddress((void**)&wi,  g_wi);    cudaGetSymbolAddress((void**)&wo,  g_wo);
    cudaGetSymbolAddress((void**)&gsh, g_gss_hi); cudaGetSymbolAddress((void**)&gsl, g_gss_lo);

    const size_t WG_OFF = (size_t)2 * DINNER * DMODEL;

    // 1) precision prep
    {
        int n;
        n = TOK * DMODEL;
        split8h_kernel<<<(n / 8 + 255) / 256, 256>>>((const float4*)x, (uint4*)xh, (uint4*)xl, n / 8);
        n = 2 * DINNER * DMODEL;
        conv8_kernel<<<(n / 8 + 255) / 256, 256>>>((const float4*)W_in, (uint4*)wi, n / 8);
        n = DINNER * DMODEL;
        conv8_kernel<<<(n / 8 + 255) / 256, 256>>>((const float4*)W_gate, (uint4*)(wi + WG_OFF), n / 8);
        n = DMODEL * DINNER;
        conv8_kernel<<<(n / 8 + 255) / 256, 256>>>((const float4*)W_out, (uint4*)wo, n / 8);
    }

    // 2) fused in-proj + gate GEMM (N = 6144)
    gemm_mma<0, 128><<<dim3(NIN / 128, TOK / 128), 256, SMEMT(128)>>>(
        xh, xl, wi, b_in, b_gate, nullptr, NIN, DMODEL);

    // 3) chunked selective scan
    scanA_kernel<<<4096, 256>>>(A_log, B_mat);
    scanB_kernel<<<NSS / 256, 256>>>();
    scanC_kernel<<<4096, 256>>>(A_log, B_mat, C_mat, D_vec);

    // 4) out = gss @ W_out^T + b_out  (BM=64 -> 256 CTAs)
    gemm_mma<2, 64><<<dim3(DMODEL / 128, TOK / 64), 256, SMEMT(64)>>>(
        gsh, gsl, wo, b_out, nullptr, out, DMODEL, DINNER);
}

// round 7
// speedup vs baseline: 4.3075x; 1.2865x over previous
#include <cuda_runtime.h>
#include <cuda_fp16.h>
#include <cstdint>

// Problem constants
#define TOK     2048
#define DMODEL  1024
#define DINNER  2048
#define DSTATE  16
#define SEQLEN  1024
#define NBATCH  2
#define NIN     (3 * DINNER)   // 6144 fused cols
#define CHK     16
#define CHL     (SEQLEN / CHK)
#define NSLOT   (NBATCH * DINNER)
#define NSS     (NSLOT * DSTATE)

// ---------------------------------------------------------------------------
// Device-global scratch
// ---------------------------------------------------------------------------
__device__ float g_xproj[TOK * DINNER];
__device__ float g_delta[TOK * DINNER];
__device__ float g_gate [TOK * DINNER];

__device__ float g_P [CHK * NSS];
__device__ float g_q [CHK * NSS];
__device__ float g_h0[CHK * NSS];

__device__ __half g_x  [TOK * DMODEL];       // x, fp16
__device__ __half g_wi [NIN * DMODEL];       // W_in ++ W_gate, fp16
__device__ __half g_wo [DMODEL * DINNER];    // W_out, fp16
__device__ __half g_gss[TOK * DINNER];       // gated scan output, fp16

// ---------------------------------------------------------------------------
// PTX helpers
// ---------------------------------------------------------------------------
__device__ __forceinline__ uint32_t smem_u32(const void* p) {
    uint32_t a;
    asm("{ .reg .u64 t; cvta.to.shared.u64 t, %1; cvt.u32.u64 %0, t; }" : "=r"(a) : "l"(p));
    return a;
}
__device__ __forceinline__ void cpa16(uint32_t s, const void* g) {
    asm volatile("cp.async.cg.shared.global [%0], [%1], 16;" :: "r"(s), "l"(g) : "memory");
}
__device__ __forceinline__ void cpa_commit() {
    asm volatile("cp.async.commit_group;" ::: "memory");
}
template <int N>
__device__ __forceinline__ void cpa_wait() {
    asm volatile("cp.async.wait_group %0;" :: "n"(N) : "memory");
}
__device__ __forceinline__ void ldsm4(uint32_t& r0, uint32_t& r1, uint32_t& r2,
                                      uint32_t& r3, uint32_t a) {
    asm volatile("ldmatrix.sync.aligned.m8n8.x4.shared.b16 {%0,%1,%2,%3}, [%4];"
                 : "=r"(r0), "=r"(r1), "=r"(r2), "=r"(r3) : "r"(a));
}
__device__ __forceinline__ void mma16816(float* d, const uint32_t* a, const uint32_t* b) {
    asm volatile(
        "mma.sync.aligned.m16n8k16.row.col.f32.f16.f16.f32 "
        "{%0,%1,%2,%3}, {%4,%5,%6,%7}, {%8,%9}, {%0,%1,%2,%3};"
        : "+f"(d[0]), "+f"(d[1]), "+f"(d[2]), "+f"(d[3])
        : "r"(a[0]), "r"(a[1]), "r"(a[2]), "r"(a[3]), "r"(b[0]), "r"(b[1]));
}

// Fast exp on FMA/ALU pipes (GEMM epilogue sigmoid only)
__device__ __forceinline__ float fexp(float z) {
    float nf = rintf(z * 1.4426950408889634f);
    float r  = fmaf(nf, -0.693145751953125f, z);
    r        = fmaf(nf, -1.42860677e-6f, r);
    float p  = 1.0f / 720.0f;
    p = fmaf(p, r, 1.0f / 120.0f);
    p = fmaf(p, r, 1.0f / 24.0f);
    p = fmaf(p, r, 1.0f / 6.0f);
    p = fmaf(p, r, 0.5f);
    p = fmaf(p, r, 1.0f);
    p = fmaf(p, r, 1.0f);
    float s = __int_as_float(((int)nf + 127) << 23);
    return p * s;
}

// ---------------------------------------------------------------------------
// SMEM: stage = A (BM rows) ++ W (128 rows), 80B rows, double buffered
// ---------------------------------------------------------------------------
#define ROWB 80
#define SMEMT(BM) (2 * ((BM) * ROWB + 128 * ROWB) + 512)

template <int ROWS>
__device__ __forceinline__ void tile_cpasync(const __half* __restrict__ g,
                                             int rowBase, int kt, int ld,
                                             uint32_t sdst, int tid) {
#pragma unroll
    for (int i = 0; i < ROWS / 64; i++) {
        int seg = tid + i * 256;
        int r   = seg >> 2;
        int c   = seg & 3;
        cpa16(sdst + r * ROWB + c * 16,
              g + (size_t)(rowBase + r) * ld + kt + c * 8);
    }
}

// ---------------------------------------------------------------------------
// fp16 GEMM: C = A @ W^T + bias
// EPI 0 (N=6144): xproj | relu->delta | sigmoid->gate
// EPI 2: +bias -> Cout
// ---------------------------------------------------------------------------
template <int EPI, int BM>
__global__ void __launch_bounds__(256, 2)
gemm_mma(const __half* __restrict__ A, const __half* __restrict__ W,
         const float* __restrict__ biasA, const float* __restrict__ biasB,
         float* __restrict__ Cout, int N, int K)
{
    constexpr int MI     = BM / 32;
    constexpr int ATILE  = BM * ROWB;
    constexpr int BTILE  = 128 * ROWB;
    constexpr int STAGE  = ATILE + BTILE;
    constexpr int BIASOF = 2 * STAGE;

    extern __shared__ char smem[];
    uint32_t sbase = smem_u32(smem);

    const int tid = threadIdx.x;
    const int wid = tid >> 5;
    const int l   = tid & 31;
    const int wm  = wid >> 2;
    const int wn  = wid & 3;
    const int mo  = wm * (BM / 2);
    const int no  = wn * 32;

    const int rowBase = blockIdx.y * BM;
    const int colBase = blockIdx.x * 128;

    if (tid < 128) {
        float bv;
        if (EPI == 0)
            bv = (colBase < 2 * DINNER) ? biasA[colBase + tid]
                                        : biasB[colBase - 2 * DINNER + tid];
        else
            bv = biasA[colBase + tid];
        *reinterpret_cast<float*>(smem + BIASOF + tid * 4) = bv;
    }

    const uint32_t aRow = (uint32_t)((mo + (l & 15)) * ROWB + ((l >> 4) * 16));
    const uint32_t bRow = (uint32_t)((no + (l & 7) + ((l & 16) ? 8 : 0)) * ROWB
                                     + (((l >> 3) & 1) * 16));

    float acc[MI][4][4];
#pragma unroll
    for (int mi = 0; mi < MI; mi++)
#pragma unroll
        for (int ni = 0; ni < 4; ni++)
#pragma unroll
            for (int r = 0; r < 4; r++) acc[mi][ni][r] = 0.0f;

    const int NC = K / 32;

    {
        uint32_t st = sbase;
        tile_cpasync<BM >(A, rowBase, 0, K, st,         tid);
        tile_cpasync<128>(W, colBase, 0, K, st + ATILE, tid);
        cpa_commit();
    }

    for (int c = 0; c < NC; c++) {
        if (c + 1 < NC) {
            uint32_t st = sbase + ((c + 1) & 1) * STAGE;
            int kt = (c + 1) * 32;
            tile_cpasync<BM >(A, rowBase, kt, K, st,         tid);
            tile_cpasync<128>(W, colBase, kt, K, st + ATILE, tid);
            cpa_commit();
            cpa_wait<1>();
        } else {
            cpa_wait<0>();
        }
        __syncthreads();

        uint32_t st = sbase + (c & 1) * STAGE;
#pragma unroll
        for (int ks = 0; ks < 2; ks++) {
            uint32_t ah[MI][4], bh[8];
#pragma unroll
            for (int mi = 0; mi < MI; mi++) {
                uint32_t ad = st + aRow + mi * (16 * ROWB) + ks * 32;
                ldsm4(ah[mi][0], ah[mi][1], ah[mi][2], ah[mi][3], ad);
            }
#pragma unroll
            for (int np = 0; np < 2; np++) {
                uint32_t bd = st + ATILE + bRow + np * (16 * ROWB) + ks * 32;
                ldsm4(bh[np * 4 + 0], bh[np * 4 + 1], bh[np * 4 + 2], bh[np * 4 + 3], bd);
            }
#pragma unroll
            for (int mi = 0; mi < MI; mi++)
#pragma unroll
                for (int ni = 0; ni < 4; ni++)
                    mma16816(acc[mi][ni], ah[mi], &bh[ni * 2]);
        }
        __syncthreads();
    }

    const float* sb = reinterpret_cast<const float*>(smem + BIASOF);
    const int g  = l >> 2;
    const int t4 = l & 3;
#pragma unroll
    for (int mi = 0; mi < MI; mi++) {
#pragma unroll
        for (int ni = 0; ni < 4; ni++) {
            int bc   = no + ni * 8 + 2 * t4;
            int col  = colBase + bc;
            int row0 = rowBase + mo + mi * 16 + g;
            int row1 = row0 + 8;
            float2 v0, v1;
            v0.x = acc[mi][ni][0] + sb[bc];
            v0.y = acc[mi][ni][1] + sb[bc + 1];
            v1.x = acc[mi][ni][2] + sb[bc];
            v1.y = acc[mi][ni][3] + sb[bc + 1];
            if (EPI == 0) {
                if (colBase < DINNER) {
                    *reinterpret_cast<float2*>(&g_xproj[(size_t)row0 * DINNER + col]) = v0;
                    *reinterpret_cast<float2*>(&g_xproj[(size_t)row1 * DINNER + col]) = v1;
                } else if (colBase < 2 * DINNER) {
                    v0.x = fmaxf(v0.x, 0.f); v0.y = fmaxf(v0.y, 0.f);
                    v1.x = fmaxf(v1.x, 0.f); v1.y = fmaxf(v1.y, 0.f);
                    int cc = col - DINNER;
                    *reinterpret_cast<float2*>(&g_delta[(size_t)row0 * DINNER + cc]) = v0;
                    *reinterpret_cast<float2*>(&g_delta[(size_t)row1 * DINNER + cc]) = v1;
                } else {
                    v0.x = 1.f / (1.f + fexp(-v0.x));
                    v0.y = 1.f / (1.f + fexp(-v0.y));
                    v1.x = 1.f / (1.f + fexp(-v1.x));
                    v1.y = 1.f / (1.f + fexp(-v1.y));
                    int cc = col - 2 * DINNER;
                    *reinterpret_cast<float2*>(&g_gate[(size_t)row0 * DINNER + cc]) = v0;
                    *reinterpret_cast<float2*>(&g_gate[(size_t)row1 * DINNER + cc]) = v1;
                }
            } else {
                *reinterpret_cast<float2*>(&Cout[(size_t)row0 * N + col]) = v0;
                *reinterpret_cast<float2*>(&Cout[(size_t)row1 * N + col]) = v1;
            }
        }
    }
}

// fp32 -> fp16 convert (8 elems / thread)
__global__ void __launch_bounds__(256)
conv8_kernel(const float4* __restrict__ src, uint4* __restrict__ dst, int n8)
{
    int i = blockIdx.x * blockDim.x + threadIdx.x;
    if (i >= n8) return;
    float4 u = src[2 * i];
    float4 v = src[2 * i + 1];
    __half2 h0 = __floats2half2_rn(u.x, u.y);
    __half2 h1 = __floats2half2_rn(u.z, u.w);
    __half2 h2 = __floats2half2_rn(v.x, v.y);
    __half2 h3 = __floats2half2_rn(v.z, v.w);
    uint4 o;
    o.x = *reinterpret_cast<uint32_t*>(&h0);
    o.y = *reinterpret_cast<uint32_t*>(&h1);
    o.z = *reinterpret_cast<uint32_t*>(&h2);
    o.w = *reinterpret_cast<uint32_t*>(&h3);
    dst[i] = o;
}

// ---------------------------------------------------------------------------
// Chunked selective scan
// ---------------------------------------------------------------------------
__global__ void __launch_bounds__(256)
scanA_kernel(const float* __restrict__ A_log, const float* __restrict__ B_mat)
{
    int gidx  = blockIdx.x * 16 + (threadIdx.x >> 4);
    int s     = threadIdx.x & 15;
    int chunk = gidx >> 12;
    int slot  = gidx & (NSLOT - 1);
    int b     = slot >> 11;
    int ch    = slot & (DINNER - 1);

    float As = -__expf(A_log[ch * DSTATE + s]);
    float Bs = B_mat[ch * DSTATE + s];

    float P = 1.0f, q = 0.0f;
    size_t base = (size_t)b * SEQLEN * DINNER + (size_t)chunk * CHL * DINNER + ch;

#pragma unroll 4
    for (int t = 0; t < CHL; t++) {
        size_t idx = base + (size_t)t * DINNER;
        float dt = g_delta[idx];
        float xt = g_xproj[idx];
        float a  = __expf(As * dt);
        q = fmaf(q, a, (xt * dt) * Bs);
        P *= a;
    }
    g_P[(size_t)gidx * DSTATE + s] = P;
    g_q[(size_t)gidx * DSTATE + s] = q;
}

__global__ void __launch_bounds__(256)
scanB_kernel()
{
    int i = blockIdx.x * 256 + threadIdx.x;
    float h = 0.0f;
#pragma unroll
    for (int k = 0; k < CHK; k++) {
        g_h0[(size_t)k * NSS + i] = h;
        h = fmaf(g_P[(size_t)k * NSS + i], h, g_q[(size_t)k * NSS + i]);
    }
}

__global__ void __launch_bounds__(256)
scanC_kernel(const float* __restrict__ A_log, const float* __restrict__ B_mat,
             const float* __restrict__ C_mat, const float* __restrict__ D_vec)
{
    int gidx  = blockIdx.x * 16 + (threadIdx.x >> 4);
    int s     = threadIdx.x & 15;
    int chunk = gidx >> 12;
    int slot  = gidx & (NSLOT - 1);
    int b     = slot >> 11;
    int ch    = slot & (DINNER - 1);

    float As  = -__expf(A_log[ch * DSTATE + s]);
    float Bs  = B_mat[ch * DSTATE + s];
    float cs  = C_mat[s];
    float Dch = D_vec[ch];

    float h = g_h0[(size_t)gidx * DSTATE + s];
    size_t base = (size_t)b * SEQLEN * DINNER + (size_t)chunk * CHL * DINNER + ch;

#pragma unroll 4
    for (int t = 0; t < CHL; t++) {
        size_t idx = base + (size_t)t * DINNER;
        float dt = g_delta[idx];
        float xt = g_xproj[idx];
        float a  = __expf(As * dt);
        h = fmaf(h, a, (xt * dt) * Bs);
        float p = h * cs;
        p += __shfl_xor_sync(0xffffffffu, p, 1);
        p += __shfl_xor_sync(0xffffffffu, p, 2);
        p += __shfl_xor_sync(0xffffffffu, p, 4);
        p += __shfl_xor_sync(0xffffffffu, p, 8);
        if (s == 0) {
            float v = g_gate[idx] * (p + xt * Dch);
            g_gss[idx] = __float2half(v);
        }
    }
}

// ---------------------------------------------------------------------------
extern "C" void kernel_launch(void* const* d_in, const int* in_sizes, int n_in,
                              void* d_out, int out_size)
{
    const float* x      = (const float*)d_in[0];
    const float* W_in   = (const float*)d_in[1];
    const float* b_in   = (const float*)d_in[2];
    const float* W_gate = (const float*)d_in[3];
    const float* b_gate = (const float*)d_in[4];
    const float* W_out  = (const float*)d_in[5];
    const float* b_out  = (const float*)d_in[6];
    const float* A_log  = (const float*)d_in[7];
    const float* B_mat  = (const float*)d_in[8];
    const float* C_mat  = (const float*)d_in[9];
    const float* D_vec  = (const float*)d_in[10];
    float* out = (float*)d_out;

    cudaFuncSetAttribute((const void*)gemm_mma<0, 128>,
                         cudaFuncAttributeMaxDynamicSharedMemorySize, SMEMT(128));
    cudaFuncSetAttribute((const void*)gemm_mma<2, 64>,
                         cudaFuncAttributeMaxDynamicSharedMemorySize, SMEMT(64));

    __half *xh, *wi, *wo, *gs;
    cudaGetSymbolAddress((void**)&xh, g_x);
    cudaGetSymbolAddress((void**)&wi, g_wi);
    cudaGetSymbolAddress((void**)&wo, g_wo);
    cudaGetSymbolAddress((void**)&gs, g_gss);

    const size_t WG_OFF = (size_t)2 * DINNER * DMODEL;

    // 1) fp32 -> fp16 converts
    {
        int n;
        n = TOK * DMODEL;
        conv8_kernel<<<(n / 8 + 255) / 256, 256>>>((const float4*)x, (uint4*)xh, n / 8);
        n = 2 * DINNER * DMODEL;
        conv8_kernel<<<(n / 8 + 255) / 256, 256>>>((const float4*)W_in, (uint4*)wi, n / 8);
        n = DINNER * DMODEL;
        conv8_kernel<<<(n / 8 + 255) / 256, 256>>>((const float4*)W_gate, (uint4*)(wi + WG_OFF), n / 8);
        n = DMODEL * DINNER;
        conv8_kernel<<<(n / 8 + 255) / 256, 256>>>((const float4*)W_out, (uint4*)wo, n / 8);
    }

    // 2) fused in-proj + gate GEMM (N = 6144)
    gemm_mma<0, 128><<<dim3(NIN / 128, TOK / 128), 256, SMEMT(128)>>>(
        xh, wi, b_in, b_gate, nullptr, NIN, DMODEL);

    // 3) chunked selective scan
    scanA_kernel<<<4096, 256>>>(A_log, B_mat);
    scanB_kernel<<<NSS / 256, 256>>>();
    scanC_kernel<<<4096, 256>>>(A_log, B_mat, C_mat, D_vec);

    // 4) out = gss @ W_out^T + b_out  (BM=64 -> 256 CTAs)
    gemm_mma<2, 64><<<dim3(DMODEL / 128, TOK / 64), 256, SMEMT(64)>>>(
        gs, wo, b_out, nullptr, out, DMODEL, DINNER);
}